// round 5
// baseline (speedup 1.0000x reference)
#include <cuda_runtime.h>
#include <math_constants.h>

// ---------------- problem constants ----------------
#define BB    64      // batch
#define NTOK  2305    // tokens incl. global token
#define NF    2304    // feature tokens (N-1)
#define DD    256     // channel dim
#define CC    128     // CLUSTER_DIM
#define KK    64      // NUM_CLUSTERS
#define KA    65      // K+1 (with dustbin)
#define NITER 5
#define OUTD  (DD + KK*CC)   // 8448

#define LOG_A (-4.174387269895637f)   // -log(65)
#define LOG_B (-7.742402021815781f)   // -log(2304)

// ---------------- scratch (device globals; no allocs allowed) ----------------
__device__ float g_f[(size_t)BB*NF*CC];       // 75.5 MB  f = fi @ Wf^T + b
__device__ float g_M[(size_t)BB*KA*NF];       // 38.3 MB  M = s_aug / reg
__device__ float g_u[BB*KA];
__device__ float g_v[BB*NF];
__device__ float g_t[BB*DD];
__device__ float g_vagg[(size_t)BB*KK*CC];    // 2 MB
__device__ float g_sanorm[KK*DD];
__device__ float g_invnorm[BB*NF];

// ---------------- helpers ----------------
__device__ __forceinline__ float warpMax(float v){
    #pragma unroll
    for (int o = 16; o; o >>= 1) v = fmaxf(v, __shfl_xor_sync(0xffffffffu, v, o));
    return v;
}
__device__ __forceinline__ float warpSum(float v){
    #pragma unroll
    for (int o = 16; o; o >>= 1) v += __shfl_xor_sync(0xffffffffu, v, o);
    return v;
}

// ================= 1) row norms: sa_norm + 1/||fi|| =================
// one warp per row; rows [0,64) = score_anchors, rows [64, 64+B*NF) = fi rows
__global__ __launch_bounds__(256) void k_norms(const float* __restrict__ x,
                                               const float* __restrict__ sa)
{
    int warp = threadIdx.x >> 5;
    int lane = threadIdx.x & 31;
    long long row = (long long)blockIdx.x * 8 + warp;
    if (row >= 64 + (long long)BB * NF) return;

    if (row < 64) {
        const float4* p = (const float4*)(sa + (size_t)row * DD);
        float4 a = p[lane], b = p[lane + 32];
        float ss = a.x*a.x + a.y*a.y + a.z*a.z + a.w*a.w
                 + b.x*b.x + b.y*b.y + b.z*b.z + b.w*b.w;
        ss = warpSum(ss);
        float inv = 1.0f / fmaxf(sqrtf(ss), 1e-12f);
        float4* d = (float4*)(g_sanorm + (size_t)row * DD);
        a.x*=inv; a.y*=inv; a.z*=inv; a.w*=inv;
        b.x*=inv; b.y*=inv; b.z*=inv; b.w*=inv;
        d[lane] = a; d[lane + 32] = b;
    } else {
        long long r = row - 64;
        int b = (int)(r / NF), n = (int)(r % NF);
        const float4* p = (const float4*)(x + ((size_t)b*NTOK + n + 1) * DD);
        float4 v1 = p[lane], v2 = p[lane + 32];
        float ss = v1.x*v1.x + v1.y*v1.y + v1.z*v1.z + v1.w*v1.w
                 + v2.x*v2.x + v2.y*v2.y + v2.z*v2.z + v2.w*v2.w;
        ss = warpSum(ss);
        if (lane == 0) g_invnorm[r] = 1.0f / fmaxf(sqrtf(ss), 1e-12f);
    }
}

// ================= 2) token projection: t = x[:,0] @ Wt^T + bt =================
__global__ __launch_bounds__(256) void k_token(const float* __restrict__ x,
                                               const float* __restrict__ tw,
                                               const float* __restrict__ tb)
{
    int b = blockIdx.x, j = threadIdx.x;
    __shared__ float4 xs[64];
    if (j < 64) xs[j] = ((const float4*)(x + (size_t)b * NTOK * DD))[j];
    __syncthreads();
    const float4* w4 = (const float4*)(tw + (size_t)j * DD);
    float acc = tb[j];
    #pragma unroll 8
    for (int d = 0; d < 64; d++) {
        float4 wv = w4[d]; float4 xv = xs[d];
        acc += wv.x*xv.x + wv.y*xv.y + wv.z*xv.z + wv.w*xv.w;
    }
    g_t[b * DD + j] = acc;
}

// ================= 3) f GEMM: f[b,n,c] = fi @ Wf^T + bias =================
// tile: 128 rows x 128 cols (full C), BK=16, 256 threads, 8x8 per thread
__global__ __launch_bounds__(256) void k_f(const float* __restrict__ x,
                                           const float* __restrict__ w,
                                           const float* __restrict__ bias)
{
    int bid = blockIdx.x;                 // 1152 = (B*NF)/128, never spans batches (2304%128==0)
    int b  = bid / 18;
    int n0 = (bid % 18) * 128;
    const float* A = x + ((size_t)b * NTOK + 1 + n0) * DD;   // rows stride DD

    __shared__ float As[16][132];   // As[kk][row]
    __shared__ float Bs[16][132];   // Bs[kk][c] = w[c*DD + k0+kk]

    int tid = threadIdx.x;
    int tr = tid >> 4, tc = tid & 15;
    float acc[8][8];
    #pragma unroll
    for (int i = 0; i < 8; i++)
        #pragma unroll
        for (int j = 0; j < 8; j++) acc[i][j] = 0.f;

    for (int k0 = 0; k0 < DD; k0 += 16) {
        #pragma unroll
        for (int it = 0; it < 2; it++) {
            int idx = tid + it * 256;          // 0..511
            int row = idx >> 2, c4 = (idx & 3) * 4;
            float4 v = *(const float4*)(A + (size_t)row * DD + k0 + c4);
            As[c4+0][row] = v.x; As[c4+1][row] = v.y;
            As[c4+2][row] = v.z; As[c4+3][row] = v.w;
        }
        #pragma unroll
        for (int it = 0; it < 2; it++) {
            int idx = tid + it * 256;
            int c = idx >> 2, c4 = (idx & 3) * 4;
            float4 v = *(const float4*)(w + (size_t)c * DD + k0 + c4);
            Bs[c4+0][c] = v.x; Bs[c4+1][c] = v.y;
            Bs[c4+2][c] = v.z; Bs[c4+3][c] = v.w;
        }
        __syncthreads();
        #pragma unroll
        for (int kk = 0; kk < 16; kk++) {
            float a[8], bb[8];
            *(float4*)(a)    = *(const float4*)&As[kk][tr*8];
            *(float4*)(a+4)  = *(const float4*)&As[kk][tr*8+4];
            *(float4*)(bb)   = *(const float4*)&Bs[kk][tc*8];
            *(float4*)(bb+4) = *(const float4*)&Bs[kk][tc*8+4];
            #pragma unroll
            for (int i = 0; i < 8; i++)
                #pragma unroll
                for (int j = 0; j < 8; j++) acc[i][j] += a[i]*bb[j];
        }
        __syncthreads();
    }

    float bi[8];
    *(float4*)(bi)   = *(const float4*)(bias + tc*8);
    *(float4*)(bi+4) = *(const float4*)(bias + tc*8 + 4);
    float* out = g_f + ((size_t)b * NF + n0) * CC;
    #pragma unroll
    for (int i = 0; i < 8; i++) {
        float v0[8];
        #pragma unroll
        for (int j = 0; j < 8; j++) v0[j] = acc[i][j] + bi[j];
        float* dst = out + (size_t)(tr*8 + i) * CC + tc*8;
        *(float4*)dst       = *(float4*)(v0);
        *(float4*)(dst + 4) = *(float4*)(v0 + 4);
    }
}

// ================= 4) score GEMM: M[b,k,n] = (sa_n . fi)*invn*sharp/reg =================
// per batch: 64(k) x 128(n) tile, BK=32, 256 threads, 4x8 per thread
__global__ __launch_bounds__(256) void k_s(const float* __restrict__ x,
                                           const float* __restrict__ lsh)
{
    int n0 = blockIdx.x * 128;     // 18 tiles
    int b  = blockIdx.y;
    float scale = __expf(lsh[0]) / 0.1f;

    __shared__ float AsT[32][68];    // AsT[d][k]
    __shared__ float BsT[32][132];   // BsT[d][nn]

    int tid = threadIdx.x;
    int trK = tid >> 4, tcN = tid & 15;
    float acc[4][8];
    #pragma unroll
    for (int i = 0; i < 4; i++)
        #pragma unroll
        for (int j = 0; j < 8; j++) acc[i][j] = 0.f;

    const float* fib = x + ((size_t)b * NTOK + 1 + n0) * DD;

    for (int d0 = 0; d0 < DD; d0 += 32) {
        #pragma unroll
        for (int it = 0; it < 2; it++) {          // 64x32 sa tile
            int idx = tid + it * 256;
            int k = idx >> 3, d4 = (idx & 7) * 4;
            float4 v = *(const float4*)(g_sanorm + (size_t)k * DD + d0 + d4);
            AsT[d4+0][k] = v.x; AsT[d4+1][k] = v.y;
            AsT[d4+2][k] = v.z; AsT[d4+3][k] = v.w;
        }
        #pragma unroll
        for (int it = 0; it < 4; it++) {          // 128x32 fi tile
            int idx = tid + it * 256;
            int nn = idx >> 3, d4 = (idx & 7) * 4;
            float4 v = *(const float4*)(fib + (size_t)nn * DD + d0 + d4);
            BsT[d4+0][nn] = v.x; BsT[d4+1][nn] = v.y;
            BsT[d4+2][nn] = v.z; BsT[d4+3][nn] = v.w;
        }
        __syncthreads();
        #pragma unroll
        for (int d = 0; d < 32; d++) {
            float a[4], bb[8];
            *(float4*)(a)    = *(const float4*)&AsT[d][trK*4];
            *(float4*)(bb)   = *(const float4*)&BsT[d][tcN*8];
            *(float4*)(bb+4) = *(const float4*)&BsT[d][tcN*8+4];
            #pragma unroll
            for (int i = 0; i < 4; i++)
                #pragma unroll
                for (int j = 0; j < 8; j++) acc[i][j] += a[i]*bb[j];
        }
        __syncthreads();
    }

    float inv[8];
    *(float4*)(inv)   = *(const float4*)(g_invnorm + (size_t)b*NF + n0 + tcN*8);
    *(float4*)(inv+4) = *(const float4*)(g_invnorm + (size_t)b*NF + n0 + tcN*8 + 4);
    #pragma unroll
    for (int i = 0; i < 4; i++) {
        int k = trK*4 + i;
        float v0[8];
        #pragma unroll
        for (int j = 0; j < 8; j++) v0[j] = acc[i][j] * inv[j] * scale;
        float* dst = g_M + ((size_t)b * KA + k) * NF + n0 + tcN*8;
        *(float4*)dst       = *(float4*)(v0);
        *(float4*)(dst + 4) = *(float4*)(v0 + 4);
    }
}

// ================= 5) init: v = 0, dustbin row of M =================
__global__ __launch_bounds__(256) void k_init(const float* __restrict__ dust)
{
    int i = blockIdx.x * 256 + threadIdx.x;
    if (i < BB * NF) {
        g_v[i] = 0.f;
        int b = i / NF, n = i % NF;
        g_M[((size_t)b * KA + KK) * NF + n] = dust[0] / 0.1f;
    }
}

// ================= 6) Sinkhorn u-update: u[b,k] = LOG_A - lse_n(M+v) =================
__global__ __launch_bounds__(256) void k_u()
{
    int bk = blockIdx.x;              // B*KA = 4160
    int b  = bk / KA;
    const float* Mr = g_M + (size_t)bk * NF;
    const float* vr = g_v + (size_t)b * NF;
    int tid = threadIdx.x;

    float loc[9];
    float mx = -CUDART_INF_F;
    #pragma unroll
    for (int it = 0; it < 9; it++) {
        int n = tid + it * 256;
        float val = Mr[n] + vr[n];
        loc[it] = val;
        mx = fmaxf(mx, val);
    }
    __shared__ float red[8];
    mx = warpMax(mx);
    if ((tid & 31) == 0) red[tid >> 5] = mx;
    __syncthreads();
    if (tid < 8) {
        float m2 = red[tid];
        #pragma unroll
        for (int o = 4; o; o >>= 1) m2 = fmaxf(m2, __shfl_xor_sync(0xffu, m2, o));
        red[tid] = m2;
    }
    __syncthreads();
    mx = red[0];

    float s = 0.f;
    #pragma unroll
    for (int it = 0; it < 9; it++) s += __expf(loc[it] - mx);
    s = warpSum(s);
    __syncthreads();                       // protect red reuse
    if ((tid & 31) == 0) red[tid >> 5] = s;
    __syncthreads();
    if (tid == 0) {
        float tot = 0.f;
        #pragma unroll
        for (int i = 0; i < 8; i++) tot += red[i];
        g_u[bk] = LOG_A - (mx + __logf(tot));
    }
}

// ================= 7) Sinkhorn v-update: v[b,n] = LOG_B - lse_k(M+u) =================
__global__ __launch_bounds__(256) void k_v()
{
    int bi = blockIdx.x;              // B*9 = 576
    int b  = bi / 9;
    int n  = (bi % 9) * 256 + threadIdx.x;
    __shared__ float us[KA];
    if (threadIdx.x < KA) us[threadIdx.x] = g_u[b * KA + threadIdx.x];
    __syncthreads();
    const float* Mc = g_M + (size_t)b * KA * NF + n;
    float mx = -CUDART_INF_F;
    #pragma unroll
    for (int k = 0; k < KA; k++) mx = fmaxf(mx, Mc[(size_t)k * NF] + us[k]);
    float s = 0.f;
    #pragma unroll
    for (int k = 0; k < KA; k++) s += __expf(Mc[(size_t)k * NF] + us[k] - mx);
    g_v[b * NF + n] = LOG_B - (mx + __logf(s));
}

// ================= 8) aggregate: v_agg = p@f - psum*agg_anchors =================
// grid (2, B): block = (batch, c-half). 64(k) x 64(c) output, n-loop in tiles of 32.
__global__ __launch_bounds__(256) void k_agg(const float* __restrict__ aggA)
{
    int ch = blockIdx.x;              // 0/1 -> c offset
    int b  = blockIdx.y;
    __shared__ float ps[64][33];      // p tile [k][nn]
    __shared__ float fs[32][68];      // f tile [nn][c]
    __shared__ float uc[64];
    __shared__ float psump[64][4];
    __shared__ float psum_s[64];

    int tid = threadIdx.x;
    if (tid < 64) uc[tid] = g_u[b * KA + tid];
    __syncthreads();

    int pk = tid >> 2;                // 0..63
    int pq = (tid & 3) * 8;           // 0,8,16,24
    int trK = tid >> 4, tcC = tid & 15;
    float acc[4][4];
    #pragma unroll
    for (int i = 0; i < 4; i++)
        #pragma unroll
        for (int j = 0; j < 4; j++) acc[i][j] = 0.f;
    float mypsum = 0.f;

    const float* Mb = g_M + (size_t)b * KA * NF;
    const float* vb = g_v + (size_t)b * NF;
    const float* fb = g_f + (size_t)b * NF * CC + ch * 64;
    float u_k = uc[pk];

    for (int n0 = 0; n0 < NF; n0 += 32) {
        const float* Mrow = Mb + (size_t)pk * NF + n0 + pq;
        const float* vrow = vb + n0 + pq;
        #pragma unroll
        for (int l = 0; l < 8; l++) {
            float pv = __expf(Mrow[l] + u_k + vrow[l]);
            ps[pk][pq + l] = pv;
            mypsum += pv;
        }
        #pragma unroll
        for (int it = 0; it < 2; it++) {     // 32x64 f tile = 512 float4
            int idx = tid + it * 256;
            int nn = idx >> 4, c4 = (idx & 15) * 4;
            float4 v = *(const float4*)(fb + (size_t)(n0 + nn) * CC + c4);
            *(float4*)&fs[nn][c4] = v;
        }
        __syncthreads();
        #pragma unroll
        for (int nn = 0; nn < 32; nn++) {
            float a[4], bb[4];
            #pragma unroll
            for (int i = 0; i < 4; i++) a[i] = ps[trK*4 + i][nn];
            *(float4*)bb = *(const float4*)&fs[nn][tcC*4];
            #pragma unroll
            for (int i = 0; i < 4; i++)
                #pragma unroll
                for (int j = 0; j < 4; j++) acc[i][j] += a[i]*bb[j];
        }
        __syncthreads();
    }

    psump[pk][tid & 3] = mypsum;
    __syncthreads();
    if (tid < 64)
        psum_s[tid] = psump[tid][0] + psump[tid][1] + psump[tid][2] + psump[tid][3];
    __syncthreads();

    float* out = g_vagg + (size_t)b * KK * CC + ch * 64;
    const float* ag = aggA + ch * 64;
    #pragma unroll
    for (int i = 0; i < 4; i++) {
        int k = trK*4 + i;
        float psv = psum_s[k];
        float v0[4];
        #pragma unroll
        for (int j = 0; j < 4; j++)
            v0[j] = acc[i][j] - psv * ag[(size_t)k * CC + tcC*4 + j];
        *(float4*)(out + (size_t)k * CC + tcC*4) = *(float4*)v0;
    }
}

// ================= 9) final concat + l2norm =================
__global__ __launch_bounds__(256) void k_out(float* __restrict__ out)
{
    int b = blockIdx.x, tid = threadIdx.x;
    const float* t  = g_t + (size_t)b * DD;
    const float* vg = g_vagg + (size_t)b * KK * CC;
    float ss = 0.f;
    #pragma unroll
    for (int it = 0; it < 33; it++) {
        int i = tid + it * 256;
        float v = (i < DD) ? t[i] : vg[i - DD];
        ss += v * v;
    }
    __shared__ float red[8];
    ss = warpSum(ss);
    if ((tid & 31) == 0) red[tid >> 5] = ss;
    __syncthreads();
    float tot = 0.f;
    #pragma unroll
    for (int i = 0; i < 8; i++) tot += red[i];
    float inv = 1.0f / fmaxf(sqrtf(tot), 1e-12f);
    float* o = out + (size_t)b * OUTD;
    #pragma unroll
    for (int it = 0; it < 33; it++) {
        int i = tid + it * 256;
        float v = (i < DD) ? t[i] : vg[i - DD];
        o[i] = v * inv;
    }
}

// ================= launch =================
extern "C" void kernel_launch(void* const* d_in, const int* in_sizes, int n_in,
                              void* d_out, int out_size)
{
    (void)in_sizes; (void)n_in; (void)out_size;
    const float* x    = (const float*)d_in[0];
    const float* fw   = (const float*)d_in[1];
    const float* fb   = (const float*)d_in[2];
    const float* tw   = (const float*)d_in[3];
    const float* tb   = (const float*)d_in[4];
    const float* sa   = (const float*)d_in[5];
    const float* agg  = (const float*)d_in[6];
    const float* dust = (const float*)d_in[7];
    const float* lsh  = (const float*)d_in[8];
    float* out = (float*)d_out;

    k_norms<<<(64 + BB*NF + 7) / 8, 256>>>(x, sa);
    k_token<<<BB, 256>>>(x, tw, tb);
    k_f<<<(BB*NF)/128, 256>>>(x, fw, fb);
    k_s<<<dim3(NF/128, BB), 256>>>(x, lsh);
    k_init<<<(BB*NF)/256, 256>>>(dust);
    for (int it = 0; it < NITER; it++) {
        k_u<<<BB*KA, 256>>>();
        k_v<<<BB*NF/256, 256>>>();
    }
    k_agg<<<dim3(2, BB), 256>>>(agg);
    k_out<<<BB, 256>>>(out);
}

// round 6
// speedup vs baseline: 1.1231x; 1.1231x over previous
#include <cuda_runtime.h>
#include <math_constants.h>

// ---------------- problem constants ----------------
#define BB    64      // batch
#define NTOK  2305    // tokens incl. global token
#define NF    2304    // feature tokens (N-1)
#define DD    256     // channel dim
#define CC    128     // CLUSTER_DIM
#define KK    64      // NUM_CLUSTERS
#define KA    65      // K+1 (with dustbin)
#define NITER 5
#define OUTD  (DD + KK*CC)   // 8448

#define LOG_A (-4.174387269895637f)   // -log(65)
#define LOG_B (-7.742402021815781f)   // -log(2304)

// ---------------- scratch (device globals; no allocs allowed) ----------------
__device__ float g_f[(size_t)BB*NF*CC];       // 75.5 MB  f = fi @ Wf^T + b
__device__ float g_M[(size_t)BB*KA*NF];       // 38.3 MB  M = s_aug / reg
__device__ float g_u[BB*KA];
__device__ float g_v[BB*NF];
__device__ float g_t[BB*DD];
__device__ float g_vagg[(size_t)BB*KK*CC];    // 2 MB
__device__ float g_sanorm[KK*DD];
__device__ float g_invnorm[BB*NF];

// ---------------- helpers ----------------
__device__ __forceinline__ float warpMax(float v){
    #pragma unroll
    for (int o = 16; o; o >>= 1) v = fmaxf(v, __shfl_xor_sync(0xffffffffu, v, o));
    return v;
}
__device__ __forceinline__ float warpSum(float v){
    #pragma unroll
    for (int o = 16; o; o >>= 1) v += __shfl_xor_sync(0xffffffffu, v, o);
    return v;
}

// ================= 1) row norms: sa_norm + 1/||fi|| =================
__global__ __launch_bounds__(256) void k_norms(const float* __restrict__ x,
                                               const float* __restrict__ sa)
{
    int warp = threadIdx.x >> 5;
    int lane = threadIdx.x & 31;
    long long row = (long long)blockIdx.x * 8 + warp;
    if (row >= 64 + (long long)BB * NF) return;

    if (row < 64) {
        const float4* p = (const float4*)(sa + (size_t)row * DD);
        float4 a = p[lane], b = p[lane + 32];
        float ss = a.x*a.x + a.y*a.y + a.z*a.z + a.w*a.w
                 + b.x*b.x + b.y*b.y + b.z*b.z + b.w*b.w;
        ss = warpSum(ss);
        float inv = 1.0f / fmaxf(sqrtf(ss), 1e-12f);
        float4* d = (float4*)(g_sanorm + (size_t)row * DD);
        a.x*=inv; a.y*=inv; a.z*=inv; a.w*=inv;
        b.x*=inv; b.y*=inv; b.z*=inv; b.w*=inv;
        d[lane] = a; d[lane + 32] = b;
    } else {
        long long r = row - 64;
        int b = (int)(r / NF), n = (int)(r % NF);
        const float4* p = (const float4*)(x + ((size_t)b*NTOK + n + 1) * DD);
        float4 v1 = p[lane], v2 = p[lane + 32];
        float ss = v1.x*v1.x + v1.y*v1.y + v1.z*v1.z + v1.w*v1.w
                 + v2.x*v2.x + v2.y*v2.y + v2.z*v2.z + v2.w*v2.w;
        ss = warpSum(ss);
        if (lane == 0) g_invnorm[r] = 1.0f / fmaxf(sqrtf(ss), 1e-12f);
    }
}

// ================= 2) token projection =================
__global__ __launch_bounds__(256) void k_token(const float* __restrict__ x,
                                               const float* __restrict__ tw,
                                               const float* __restrict__ tb)
{
    int b = blockIdx.x, j = threadIdx.x;
    __shared__ float4 xs[64];
    if (j < 64) xs[j] = ((const float4*)(x + (size_t)b * NTOK * DD))[j];
    __syncthreads();
    const float4* w4 = (const float4*)(tw + (size_t)j * DD);
    float acc = tb[j];
    #pragma unroll 8
    for (int d = 0; d < 64; d++) {
        float4 wv = w4[d]; float4 xv = xs[d];
        acc += wv.x*xv.x + wv.y*xv.y + wv.z*xv.z + wv.w*xv.w;
    }
    g_t[b * DD + j] = acc;
}

// ================= 3) f GEMM: f[b,n,c] = fi @ Wf^T + bias =================
// tile 128x128, BK=16, 256 threads, 8x8/thread, double-buffered
__global__ __launch_bounds__(256, 2) void k_f(const float* __restrict__ x,
                                              const float* __restrict__ w,
                                              const float* __restrict__ bias)
{
    int bid = blockIdx.x;                 // 1152 tiles, never spans batches
    int b  = bid / 18;
    int n0 = (bid % 18) * 128;
    const float* A = x + ((size_t)b * NTOK + 1 + n0) * DD;

    __shared__ float As[2][16][132];   // As[buf][kk][row]
    __shared__ float Bs[2][16][132];   // Bs[buf][kk][c]

    int tid = threadIdx.x;
    int tr = tid >> 4, tc = tid & 15;
    float acc[8][8];
    #pragma unroll
    for (int i = 0; i < 8; i++)
        #pragma unroll
        for (int j = 0; j < 8; j++) acc[i][j] = 0.f;

    // preload chunk 0 into buffer 0
    #pragma unroll
    for (int it = 0; it < 2; it++) {
        int idx = tid + it * 256;
        int row = idx >> 2, c4 = (idx & 3) * 4;
        float4 v = *(const float4*)(A + (size_t)row * DD + c4);
        As[0][c4+0][row] = v.x; As[0][c4+1][row] = v.y;
        As[0][c4+2][row] = v.z; As[0][c4+3][row] = v.w;
        float4 u = *(const float4*)(w + (size_t)row * DD + c4);
        Bs[0][c4+0][row] = u.x; Bs[0][c4+1][row] = u.y;
        Bs[0][c4+2][row] = u.z; Bs[0][c4+3][row] = u.w;
    }
    __syncthreads();

    int buf = 0;
    for (int k0 = 16; k0 <= DD; k0 += 16) {
        float4 ra[2], rb[2];
        if (k0 < DD) {
            #pragma unroll
            for (int it = 0; it < 2; it++) {
                int idx = tid + it * 256;
                int row = idx >> 2, c4 = (idx & 3) * 4;
                ra[it] = *(const float4*)(A + (size_t)row * DD + k0 + c4);
                rb[it] = *(const float4*)(w + (size_t)row * DD + k0 + c4);
            }
        }
        #pragma unroll
        for (int kk = 0; kk < 16; kk++) {
            float a[8], bb[8];
            *(float4*)(a)    = *(const float4*)&As[buf][kk][tr*8];
            *(float4*)(a+4)  = *(const float4*)&As[buf][kk][tr*8+4];
            *(float4*)(bb)   = *(const float4*)&Bs[buf][kk][tc*8];
            *(float4*)(bb+4) = *(const float4*)&Bs[buf][kk][tc*8+4];
            #pragma unroll
            for (int i = 0; i < 8; i++)
                #pragma unroll
                for (int j = 0; j < 8; j++) acc[i][j] += a[i]*bb[j];
        }
        if (k0 < DD) {
            int nb = buf ^ 1;
            #pragma unroll
            for (int it = 0; it < 2; it++) {
                int idx = tid + it * 256;
                int row = idx >> 2, c4 = (idx & 3) * 4;
                As[nb][c4+0][row] = ra[it].x; As[nb][c4+1][row] = ra[it].y;
                As[nb][c4+2][row] = ra[it].z; As[nb][c4+3][row] = ra[it].w;
                Bs[nb][c4+0][row] = rb[it].x; Bs[nb][c4+1][row] = rb[it].y;
                Bs[nb][c4+2][row] = rb[it].z; Bs[nb][c4+3][row] = rb[it].w;
            }
            __syncthreads();
            buf = nb;
        }
    }

    float bi[8];
    *(float4*)(bi)   = *(const float4*)(bias + tc*8);
    *(float4*)(bi+4) = *(const float4*)(bias + tc*8 + 4);
    float* out = g_f + ((size_t)b * NF + n0) * CC;
    #pragma unroll
    for (int i = 0; i < 8; i++) {
        float v0[8];
        #pragma unroll
        for (int j = 0; j < 8; j++) v0[j] = acc[i][j] + bi[j];
        float* dst = out + (size_t)(tr*8 + i) * CC + tc*8;
        *(float4*)dst       = *(float4*)(v0);
        *(float4*)(dst + 4) = *(float4*)(v0 + 4);
    }
}

// ================= 4) score GEMM: M[b,k,n] = (sa_n . fi)*invn*sharp/reg =================
// tile 64(k) x 256(n), BK=16, 256 threads, 8x8/thread, double-buffered.
// A fragment is a warp-broadcast (all lanes share trK).
__global__ __launch_bounds__(256, 2) void k_s(const float* __restrict__ x,
                                              const float* __restrict__ lsh)
{
    int n0 = blockIdx.x * 256;     // 9 tiles
    int b  = blockIdx.y;
    float scale = __expf(lsh[0]) / 0.1f;

    __shared__ float As[2][16][68];    // [buf][d][k]
    __shared__ float Bs[2][16][260];   // [buf][d][n]

    int tid = threadIdx.x;
    int trK = tid >> 5;        // 0..7  (k group)
    int tcN = tid & 31;        // 0..31 (n group)
    float acc[8][8];
    #pragma unroll
    for (int i = 0; i < 8; i++)
        #pragma unroll
        for (int j = 0; j < 8; j++) acc[i][j] = 0.f;

    const float* fib = x + ((size_t)b * NTOK + 1 + n0) * DD;

    // preload chunk 0
    {
        int k = tid >> 2, d4 = (tid & 3) * 4;
        float4 v = *(const float4*)(g_sanorm + (size_t)k * DD + d4);
        As[0][d4+0][k] = v.x; As[0][d4+1][k] = v.y;
        As[0][d4+2][k] = v.z; As[0][d4+3][k] = v.w;
        #pragma unroll
        for (int it = 0; it < 4; it++) {
            int idx = tid + it * 256;
            int n = idx >> 2, c4 = (idx & 3) * 4;
            float4 u = *(const float4*)(fib + (size_t)n * DD + c4);
            Bs[0][c4+0][n] = u.x; Bs[0][c4+1][n] = u.y;
            Bs[0][c4+2][n] = u.z; Bs[0][c4+3][n] = u.w;
        }
    }
    __syncthreads();

    int buf = 0;
    for (int d0 = 16; d0 <= DD; d0 += 16) {
        float4 ra; float4 rb[4];
        if (d0 < DD) {
            int k = tid >> 2, d4 = (tid & 3) * 4;
            ra = *(const float4*)(g_sanorm + (size_t)k * DD + d0 + d4);
            #pragma unroll
            for (int it = 0; it < 4; it++) {
                int idx = tid + it * 256;
                int n = idx >> 2, c4 = (idx & 3) * 4;
                rb[it] = *(const float4*)(fib + (size_t)n * DD + d0 + c4);
            }
        }
        #pragma unroll
        for (int d = 0; d < 16; d++) {
            float a[8], bb[8];
            *(float4*)(a)    = *(const float4*)&As[buf][d][trK*8];
            *(float4*)(a+4)  = *(const float4*)&As[buf][d][trK*8+4];
            *(float4*)(bb)   = *(const float4*)&Bs[buf][d][tcN*8];
            *(float4*)(bb+4) = *(const float4*)&Bs[buf][d][tcN*8+4];
            #pragma unroll
            for (int i = 0; i < 8; i++)
                #pragma unroll
                for (int j = 0; j < 8; j++) acc[i][j] += a[i]*bb[j];
        }
        if (d0 < DD) {
            int nb = buf ^ 1;
            int k = tid >> 2, d4 = (tid & 3) * 4;
            As[nb][d4+0][k] = ra.x; As[nb][d4+1][k] = ra.y;
            As[nb][d4+2][k] = ra.z; As[nb][d4+3][k] = ra.w;
            #pragma unroll
            for (int it = 0; it < 4; it++) {
                int idx = tid + it * 256;
                int n = idx >> 2, c4 = (idx & 3) * 4;
                Bs[nb][c4+0][n] = rb[it].x; Bs[nb][c4+1][n] = rb[it].y;
                Bs[nb][c4+2][n] = rb[it].z; Bs[nb][c4+3][n] = rb[it].w;
            }
            __syncthreads();
            buf = nb;
        }
    }

    float inv[8];
    *(float4*)(inv)   = *(const float4*)(g_invnorm + (size_t)b*NF + n0 + tcN*8);
    *(float4*)(inv+4) = *(const float4*)(g_invnorm + (size_t)b*NF + n0 + tcN*8 + 4);
    #pragma unroll
    for (int i = 0; i < 8; i++) {
        int k = trK*8 + i;
        float v0[8];
        #pragma unroll
        for (int j = 0; j < 8; j++) v0[j] = acc[i][j] * inv[j] * scale;
        float* dst = g_M + ((size_t)b * KA + k) * NF + n0 + tcN*8;
        *(float4*)dst       = *(float4*)(v0);
        *(float4*)(dst + 4) = *(float4*)(v0 + 4);
    }
}

// ================= 5) init: v = 0, dustbin row of M =================
__global__ __launch_bounds__(256) void k_init(const float* __restrict__ dust)
{
    int i = blockIdx.x * 256 + threadIdx.x;
    if (i < BB * NF) {
        g_v[i] = 0.f;
        int b = i / NF, n = i % NF;
        g_M[((size_t)b * KA + KK) * NF + n] = dust[0] / 0.1f;
    }
}

// ================= 6) Sinkhorn u-update =================
__global__ __launch_bounds__(256) void k_u()
{
    int bk = blockIdx.x;              // B*KA = 4160
    int b  = bk / KA;
    const float* Mr = g_M + (size_t)bk * NF;
    const float* vr = g_v + (size_t)b * NF;
    int tid = threadIdx.x;

    float loc[9];
    float mx = -CUDART_INF_F;
    #pragma unroll
    for (int it = 0; it < 9; it++) {
        int n = tid + it * 256;
        float val = Mr[n] + vr[n];
        loc[it] = val;
        mx = fmaxf(mx, val);
    }
    __shared__ float red[8];
    mx = warpMax(mx);
    if ((tid & 31) == 0) red[tid >> 5] = mx;
    __syncthreads();
    if (tid < 8) {
        float m2 = red[tid];
        #pragma unroll
        for (int o = 4; o; o >>= 1) m2 = fmaxf(m2, __shfl_xor_sync(0xffu, m2, o));
        red[tid] = m2;
    }
    __syncthreads();
    mx = red[0];

    float s = 0.f;
    #pragma unroll
    for (int it = 0; it < 9; it++) s += __expf(loc[it] - mx);
    s = warpSum(s);
    __syncthreads();
    if ((tid & 31) == 0) red[tid >> 5] = s;
    __syncthreads();
    if (tid == 0) {
        float tot = 0.f;
        #pragma unroll
        for (int i = 0; i < 8; i++) tot += red[i];
        g_u[bk] = LOG_A - (mx + __logf(tot));
    }
}

// ================= 7) Sinkhorn v-update =================
__global__ __launch_bounds__(256) void k_v()
{
    int bi = blockIdx.x;              // B*9 = 576
    int b  = bi / 9;
    int n  = (bi % 9) * 256 + threadIdx.x;
    __shared__ float us[KA];
    if (threadIdx.x < KA) us[threadIdx.x] = g_u[b * KA + threadIdx.x];
    __syncthreads();
    const float* Mc = g_M + (size_t)b * KA * NF + n;
    float mx = -CUDART_INF_F;
    #pragma unroll
    for (int k = 0; k < KA; k++) mx = fmaxf(mx, Mc[(size_t)k * NF] + us[k]);
    float s = 0.f;
    #pragma unroll
    for (int k = 0; k < KA; k++) s += __expf(Mc[(size_t)k * NF] + us[k] - mx);
    g_v[b * NF + n] = LOG_B - (mx + __logf(s));
}

// ================= 8) aggregate: v_agg = p@f - psum*agg_anchors =================
__global__ __launch_bounds__(256) void k_agg(const float* __restrict__ aggA)
{
    int ch = blockIdx.x;
    int b  = blockIdx.y;
    __shared__ float ps[64][33];
    __shared__ float fs[32][68];
    __shared__ float uc[64];
    __shared__ float psump[64][4];
    __shared__ float psum_s[64];

    int tid = threadIdx.x;
    if (tid < 64) uc[tid] = g_u[b * KA + tid];
    __syncthreads();

    int pk = tid >> 2;
    int pq = (tid & 3) * 8;
    int trK = tid >> 4, tcC = tid & 15;
    float acc[4][4];
    #pragma unroll
    for (int i = 0; i < 4; i++)
        #pragma unroll
        for (int j = 0; j < 4; j++) acc[i][j] = 0.f;
    float mypsum = 0.f;

    const float* Mb = g_M + (size_t)b * KA * NF;
    const float* vb = g_v + (size_t)b * NF;
    const float* fb = g_f + (size_t)b * NF * CC + ch * 64;
    float u_k = uc[pk];

    for (int n0 = 0; n0 < NF; n0 += 32) {
        const float* Mrow = Mb + (size_t)pk * NF + n0 + pq;
        const float* vrow = vb + n0 + pq;
        #pragma unroll
        for (int l = 0; l < 8; l++) {
            float pv = __expf(Mrow[l] + u_k + vrow[l]);
            ps[pk][pq + l] = pv;
            mypsum += pv;
        }
        #pragma unroll
        for (int it = 0; it < 2; it++) {
            int idx = tid + it * 256;
            int nn = idx >> 4, c4 = (idx & 15) * 4;
            float4 v = *(const float4*)(fb + (size_t)(n0 + nn) * CC + c4);
            *(float4*)&fs[nn][c4] = v;
        }
        __syncthreads();
        #pragma unroll
        for (int nn = 0; nn < 32; nn++) {
            float a[4], bb[4];
            #pragma unroll
            for (int i = 0; i < 4; i++) a[i] = ps[trK*4 + i][nn];
            *(float4*)bb = *(const float4*)&fs[nn][tcC*4];
            #pragma unroll
            for (int i = 0; i < 4; i++)
                #pragma unroll
                for (int j = 0; j < 4; j++) acc[i][j] += a[i]*bb[j];
        }
        __syncthreads();
    }

    psump[pk][tid & 3] = mypsum;
    __syncthreads();
    if (tid < 64)
        psum_s[tid] = psump[tid][0] + psump[tid][1] + psump[tid][2] + psump[tid][3];
    __syncthreads();

    float* out = g_vagg + (size_t)b * KK * CC + ch * 64;
    const float* ag = aggA + ch * 64;
    #pragma unroll
    for (int i = 0; i < 4; i++) {
        int k = trK*4 + i;
        float psv = psum_s[k];
        float v0[4];
        #pragma unroll
        for (int j = 0; j < 4; j++)
            v0[j] = acc[i][j] - psv * ag[(size_t)k * CC + tcC*4 + j];
        *(float4*)(out + (size_t)k * CC + tcC*4) = *(float4*)v0;
    }
}

// ================= 9) final concat + l2norm =================
__global__ __launch_bounds__(256) void k_out(float* __restrict__ out)
{
    int b = blockIdx.x, tid = threadIdx.x;
    const float* t  = g_t + (size_t)b * DD;
    const float* vg = g_vagg + (size_t)b * KK * CC;
    float ss = 0.f;
    #pragma unroll
    for (int it = 0; it < 33; it++) {
        int i = tid + it * 256;
        float v = (i < DD) ? t[i] : vg[i - DD];
        ss += v * v;
    }
    __shared__ float red[8];
    ss = warpSum(ss);
    if ((tid & 31) == 0) red[tid >> 5] = ss;
    __syncthreads();
    float tot = 0.f;
    #pragma unroll
    for (int i = 0; i < 8; i++) tot += red[i];
    float inv = 1.0f / fmaxf(sqrtf(tot), 1e-12f);
    float* o = out + (size_t)b * OUTD;
    #pragma unroll
    for (int it = 0; it < 33; it++) {
        int i = tid + it * 256;
        float v = (i < DD) ? t[i] : vg[i - DD];
        o[i] = v * inv;
    }
}

// ================= launch =================
extern "C" void kernel_launch(void* const* d_in, const int* in_sizes, int n_in,
                              void* d_out, int out_size)
{
    (void)in_sizes; (void)n_in; (void)out_size;
    const float* x    = (const float*)d_in[0];
    const float* fw   = (const float*)d_in[1];
    const float* fb   = (const float*)d_in[2];
    const float* tw   = (const float*)d_in[3];
    const float* tb   = (const float*)d_in[4];
    const float* sa   = (const float*)d_in[5];
    const float* agg  = (const float*)d_in[6];
    const float* dust = (const float*)d_in[7];
    const float* lsh  = (const float*)d_in[8];
    float* out = (float*)d_out;

    k_norms<<<(64 + BB*NF + 7) / 8, 256>>>(x, sa);
    k_token<<<BB, 256>>>(x, tw, tb);
    k_f<<<(BB*NF)/128, 256>>>(x, fw, fb);
    k_s<<<dim3(NF/256, BB), 256>>>(x, lsh);
    k_init<<<(BB*NF)/256, 256>>>(dust);
    for (int it = 0; it < NITER; it++) {
        k_u<<<BB*KA, 256>>>();
        k_v<<<BB*NF/256, 256>>>();
    }
    k_agg<<<dim3(2, BB), 256>>>(agg);
    k_out<<<BB, 256>>>(out);
}

// round 7
// speedup vs baseline: 1.2196x; 1.0859x over previous
#include <cuda_runtime.h>
#include <math_constants.h>

// ---------------- problem constants ----------------
#define BB    64      // batch
#define NTOK  2305    // tokens incl. global token
#define NF    2304    // feature tokens (N-1)
#define DD    256     // channel dim
#define CC    128     // CLUSTER_DIM
#define KK    64      // NUM_CLUSTERS
#define KA    65      // K+1 (with dustbin)
#define NITER 5
#define OUTD  (DD + KK*CC)   // 8448

#define EXP_LOG_A (1.0f/65.0f)      // exp(-log(65))
#define EXP_LOG_B (1.0f/2304.0f)    // exp(-log(2304))

// ---------------- scratch (device globals; no allocs allowed) ----------------
__device__ float g_f[(size_t)BB*NF*CC];       // 75.5 MB  f = fi @ Wf^T + b
__device__ float g_M[(size_t)BB*KA*NF];       // 38.3 MB  E = exp(s_aug / reg)
__device__ float g_eu[BB*KA];                 // exp(u)
__device__ float g_ev[BB*NF];                 // exp(v)
__device__ float g_t[BB*DD];
__device__ float g_vagg[(size_t)BB*KK*CC];    // 2 MB
__device__ float g_sanorm[KK*DD];

// ---------------- helpers ----------------
__device__ __forceinline__ float warpSum(float v){
    #pragma unroll
    for (int o = 16; o; o >>= 1) v += __shfl_xor_sync(0xffffffffu, v, o);
    return v;
}

// ================= 1) sa_norm =================
__global__ __launch_bounds__(256) void k_norms(const float* __restrict__ sa)
{
    int warp = threadIdx.x >> 5;
    int lane = threadIdx.x & 31;
    int row = blockIdx.x * 8 + warp;
    if (row >= 64) return;
    const float4* p = (const float4*)(sa + (size_t)row * DD);
    float4 a = p[lane], b = p[lane + 32];
    float ss = a.x*a.x + a.y*a.y + a.z*a.z + a.w*a.w
             + b.x*b.x + b.y*b.y + b.z*b.z + b.w*b.w;
    ss = warpSum(ss);
    float inv = 1.0f / fmaxf(sqrtf(ss), 1e-12f);
    float4* d = (float4*)(g_sanorm + (size_t)row * DD);
    a.x*=inv; a.y*=inv; a.z*=inv; a.w*=inv;
    b.x*=inv; b.y*=inv; b.z*=inv; b.w*=inv;
    d[lane] = a; d[lane + 32] = b;
}

// ================= 2) token projection =================
__global__ __launch_bounds__(256) void k_token(const float* __restrict__ x,
                                               const float* __restrict__ tw,
                                               const float* __restrict__ tb)
{
    int b = blockIdx.x, j = threadIdx.x;
    __shared__ float4 xs[64];
    if (j < 64) xs[j] = ((const float4*)(x + (size_t)b * NTOK * DD))[j];
    __syncthreads();
    const float4* w4 = (const float4*)(tw + (size_t)j * DD);
    float acc = tb[j];
    #pragma unroll 8
    for (int d = 0; d < 64; d++) {
        float4 wv = w4[d]; float4 xv = xs[d];
        acc += wv.x*xv.x + wv.y*xv.y + wv.z*xv.z + wv.w*xv.w;
    }
    g_t[b * DD + j] = acc;
}

// ================= 3) f GEMM: f[b,n,c] = fi @ Wf^T + bias =================
__global__ __launch_bounds__(256, 2) void k_f(const float* __restrict__ x,
                                              const float* __restrict__ w,
                                              const float* __restrict__ bias)
{
    int bid = blockIdx.x;
    int b  = bid / 18;
    int n0 = (bid % 18) * 128;
    const float* A = x + ((size_t)b * NTOK + 1 + n0) * DD;

    __shared__ float As[2][16][132];
    __shared__ float Bs[2][16][132];

    int tid = threadIdx.x;
    int tr = tid >> 4, tc = tid & 15;
    float acc[8][8];
    #pragma unroll
    for (int i = 0; i < 8; i++)
        #pragma unroll
        for (int j = 0; j < 8; j++) acc[i][j] = 0.f;

    #pragma unroll
    for (int it = 0; it < 2; it++) {
        int idx = tid + it * 256;
        int row = idx >> 2, c4 = (idx & 3) * 4;
        float4 v = *(const float4*)(A + (size_t)row * DD + c4);
        As[0][c4+0][row] = v.x; As[0][c4+1][row] = v.y;
        As[0][c4+2][row] = v.z; As[0][c4+3][row] = v.w;
        float4 u = *(const float4*)(w + (size_t)row * DD + c4);
        Bs[0][c4+0][row] = u.x; Bs[0][c4+1][row] = u.y;
        Bs[0][c4+2][row] = u.z; Bs[0][c4+3][row] = u.w;
    }
    __syncthreads();

    int buf = 0;
    for (int k0 = 16; k0 <= DD; k0 += 16) {
        float4 ra[2], rb[2];
        if (k0 < DD) {
            #pragma unroll
            for (int it = 0; it < 2; it++) {
                int idx = tid + it * 256;
                int row = idx >> 2, c4 = (idx & 3) * 4;
                ra[it] = *(const float4*)(A + (size_t)row * DD + k0 + c4);
                rb[it] = *(const float4*)(w + (size_t)row * DD + k0 + c4);
            }
        }
        #pragma unroll
        for (int kk = 0; kk < 16; kk++) {
            float a[8], bb[8];
            *(float4*)(a)    = *(const float4*)&As[buf][kk][tr*8];
            *(float4*)(a+4)  = *(const float4*)&As[buf][kk][tr*8+4];
            *(float4*)(bb)   = *(const float4*)&Bs[buf][kk][tc*8];
            *(float4*)(bb+4) = *(const float4*)&Bs[buf][kk][tc*8+4];
            #pragma unroll
            for (int i = 0; i < 8; i++)
                #pragma unroll
                for (int j = 0; j < 8; j++) acc[i][j] += a[i]*bb[j];
        }
        if (k0 < DD) {
            int nb = buf ^ 1;
            #pragma unroll
            for (int it = 0; it < 2; it++) {
                int idx = tid + it * 256;
                int row = idx >> 2, c4 = (idx & 3) * 4;
                As[nb][c4+0][row] = ra[it].x; As[nb][c4+1][row] = ra[it].y;
                As[nb][c4+2][row] = ra[it].z; As[nb][c4+3][row] = ra[it].w;
                Bs[nb][c4+0][row] = rb[it].x; Bs[nb][c4+1][row] = rb[it].y;
                Bs[nb][c4+2][row] = rb[it].z; Bs[nb][c4+3][row] = rb[it].w;
            }
            __syncthreads();
            buf = nb;
        }
    }

    float bi[8];
    *(float4*)(bi)   = *(const float4*)(bias + tc*8);
    *(float4*)(bi+4) = *(const float4*)(bias + tc*8 + 4);
    float* out = g_f + ((size_t)b * NF + n0) * CC;
    #pragma unroll
    for (int i = 0; i < 8; i++) {
        float v0[8];
        #pragma unroll
        for (int j = 0; j < 8; j++) v0[j] = acc[i][j] + bi[j];
        float* dst = out + (size_t)(tr*8 + i) * CC + tc*8;
        *(float4*)dst       = *(float4*)(v0);
        *(float4*)(dst + 4) = *(float4*)(v0 + 4);
    }
}

// ================= 4) score GEMM + fused fi-norm + exp:
// E[b,k,n] = exp( (sa_n . fi_n) / ||fi_n|| * sharp / reg )
__global__ __launch_bounds__(256, 2) void k_s(const float* __restrict__ x,
                                              const float* __restrict__ lsh)
{
    int n0 = blockIdx.x * 256;     // 9 tiles
    int b  = blockIdx.y;
    float scale = __expf(lsh[0]) * 10.0f;

    __shared__ float As[2][16][68];
    __shared__ float Bs[2][16][260];
    __shared__ float sspart[256][4];

    int tid = threadIdx.x;
    int trK = tid >> 5;
    int tcN = tid & 31;
    float acc[8][8];
    #pragma unroll
    for (int i = 0; i < 8; i++)
        #pragma unroll
        for (int j = 0; j < 8; j++) acc[i][j] = 0.f;
    float ssl[4] = {0.f, 0.f, 0.f, 0.f};

    const float* fib = x + ((size_t)b * NTOK + 1 + n0) * DD;
    int kA = tid >> 2, dA = (tid & 3) * 4;

    // preload chunk 0
    {
        float4 v = *(const float4*)(g_sanorm + (size_t)kA * DD + dA);
        As[0][dA+0][kA] = v.x; As[0][dA+1][kA] = v.y;
        As[0][dA+2][kA] = v.z; As[0][dA+3][kA] = v.w;
        #pragma unroll
        for (int it = 0; it < 4; it++) {
            int idx = tid + it * 256;
            int n = idx >> 2, c4 = (idx & 3) * 4;
            float4 u = *(const float4*)(fib + (size_t)n * DD + c4);
            ssl[it] += u.x*u.x + u.y*u.y + u.z*u.z + u.w*u.w;
            Bs[0][c4+0][n] = u.x; Bs[0][c4+1][n] = u.y;
            Bs[0][c4+2][n] = u.z; Bs[0][c4+3][n] = u.w;
        }
    }
    __syncthreads();

    int buf = 0;
    for (int d0 = 16; d0 <= DD; d0 += 16) {
        float4 ra; float4 rb[4];
        if (d0 < DD) {
            ra = *(const float4*)(g_sanorm + (size_t)kA * DD + d0 + dA);
            #pragma unroll
            for (int it = 0; it < 4; it++) {
                int idx = tid + it * 256;
                int n = idx >> 2, c4 = (idx & 3) * 4;
                rb[it] = *(const float4*)(fib + (size_t)n * DD + d0 + c4);
                ssl[it] += rb[it].x*rb[it].x + rb[it].y*rb[it].y
                         + rb[it].z*rb[it].z + rb[it].w*rb[it].w;
            }
        }
        #pragma unroll
        for (int d = 0; d < 16; d++) {
            float a[8], bb[8];
            *(float4*)(a)    = *(const float4*)&As[buf][d][trK*8];
            *(float4*)(a+4)  = *(const float4*)&As[buf][d][trK*8+4];
            *(float4*)(bb)   = *(const float4*)&Bs[buf][d][tcN*8];
            *(float4*)(bb+4) = *(const float4*)&Bs[buf][d][tcN*8+4];
            #pragma unroll
            for (int i = 0; i < 8; i++)
                #pragma unroll
                for (int j = 0; j < 8; j++) acc[i][j] += a[i]*bb[j];
        }
        if (d0 < DD) {
            int nb = buf ^ 1;
            As[nb][dA+0][kA] = ra.x; As[nb][dA+1][kA] = ra.y;
            As[nb][dA+2][kA] = ra.z; As[nb][dA+3][kA] = ra.w;
            #pragma unroll
            for (int it = 0; it < 4; it++) {
                int idx = tid + it * 256;
                int n = idx >> 2, c4 = (idx & 3) * 4;
                Bs[nb][c4+0][n] = rb[it].x; Bs[nb][c4+1][n] = rb[it].y;
                Bs[nb][c4+2][n] = rb[it].z; Bs[nb][c4+3][n] = rb[it].w;
            }
            __syncthreads();
            buf = nb;
        }
    }

    // exchange sum-of-squares partials
    #pragma unroll
    for (int it = 0; it < 4; it++)
        sspart[(tid >> 2) + it * 64][tid & 3] = ssl[it];
    __syncthreads();

    float invs[8];
    #pragma unroll
    for (int j = 0; j < 8; j++) {
        float4 sv = *(const float4*)&sspart[tcN*8 + j][0];
        float ss = (sv.x + sv.y) + (sv.z + sv.w);
        invs[j] = scale / fmaxf(sqrtf(ss), 1e-12f);
    }
    #pragma unroll
    for (int i = 0; i < 8; i++) {
        int k = trK*8 + i;
        float v0[8];
        #pragma unroll
        for (int j = 0; j < 8; j++) v0[j] = __expf(acc[i][j] * invs[j]);
        float* dst = g_M + ((size_t)b * KA + k) * NF + n0 + tcN*8;
        *(float4*)dst       = *(float4*)(v0);
        *(float4*)(dst + 4) = *(float4*)(v0 + 4);
    }
}

// ================= 5) init: ev = 1, dustbin row E = exp(dust/reg) =================
__global__ __launch_bounds__(256) void k_init(const float* __restrict__ dust)
{
    int i = blockIdx.x * 256 + threadIdx.x;
    if (i < BB * NF) {
        g_ev[i] = 1.0f;
        int b = i / NF, n = i % NF;
        g_M[((size_t)b * KA + KK) * NF + n] = __expf(dust[0] * 10.0f);
    }
}

// ================= 6) Sinkhorn u-update: eu = (1/65) / sum_n E*ev =================
__global__ __launch_bounds__(192) void k_u()
{
    int bk = blockIdx.x;              // B*KA = 4160
    int b  = bk / KA;
    const float4* E  = (const float4*)(g_M + (size_t)bk * NF);
    const float4* ev = (const float4*)(g_ev + (size_t)b * NF);
    int tid = threadIdx.x;
    float s = 0.f;
    #pragma unroll
    for (int it = 0; it < 3; it++) {
        int i = tid + it * 192;
        float4 e = E[i], w = ev[i];
        s += e.x*w.x + e.y*w.y + e.z*w.z + e.w*w.w;
    }
    s = warpSum(s);
    __shared__ float red[6];
    if ((tid & 31) == 0) red[tid >> 5] = s;
    __syncthreads();
    if (tid == 0) {
        float t = ((red[0]+red[1]) + (red[2]+red[3])) + (red[4]+red[5]);
        g_eu[bk] = __fdividef(EXP_LOG_A, t);
    }
}

// ================= 7) Sinkhorn v-update: ev = (1/2304) / sum_k E*eu =================
__global__ __launch_bounds__(192) void k_v()
{
    int b  = blockIdx.y;
    int n4 = blockIdx.x * 192 + threadIdx.x;   // float4 index, 576/batch (grid.x=3)
    __shared__ float eus[KA];
    if (threadIdx.x < KA) eus[threadIdx.x] = g_eu[b * KA + threadIdx.x];
    __syncthreads();
    const float4* Eb = (const float4*)(g_M + (size_t)b * KA * NF);
    float4 acc = {0.f, 0.f, 0.f, 0.f};
    #pragma unroll 5
    for (int k = 0; k < KA; k++) {
        float4 e = Eb[(size_t)k * (NF/4) + n4];
        float u = eus[k];
        acc.x += e.x * u; acc.y += e.y * u;
        acc.z += e.z * u; acc.w += e.w * u;
    }
    float4 r;
    r.x = __fdividef(EXP_LOG_B, acc.x);
    r.y = __fdividef(EXP_LOG_B, acc.y);
    r.z = __fdividef(EXP_LOG_B, acc.z);
    r.w = __fdividef(EXP_LOG_B, acc.w);
    ((float4*)(g_ev + (size_t)b * NF))[n4] = r;
}

// ================= 8) aggregate: v_agg = p@f - psum*agg_anchors, p = eu*E*ev =================
__global__ __launch_bounds__(256) void k_agg(const float* __restrict__ aggA)
{
    int ch = blockIdx.x;
    int b  = blockIdx.y;
    __shared__ float ps[64][33];
    __shared__ float fs[32][68];
    __shared__ float uc[64];
    __shared__ float psump[64][4];
    __shared__ float psum_s[64];

    int tid = threadIdx.x;
    if (tid < 64) uc[tid] = g_eu[b * KA + tid];
    __syncthreads();

    int pk = tid >> 2;
    int pq = (tid & 3) * 8;
    int trK = tid >> 4, tcC = tid & 15;
    float acc[4][4];
    #pragma unroll
    for (int i = 0; i < 4; i++)
        #pragma unroll
        for (int j = 0; j < 4; j++) acc[i][j] = 0.f;
    float mypsum = 0.f;

    const float* Eb = g_M + (size_t)b * KA * NF;
    const float* vb = g_ev + (size_t)b * NF;
    const float* fb = g_f + (size_t)b * NF * CC + ch * 64;
    float u_k = uc[pk];

    for (int n0 = 0; n0 < NF; n0 += 32) {
        const float* Erow = Eb + (size_t)pk * NF + n0 + pq;
        const float* vrow = vb + n0 + pq;
        #pragma unroll
        for (int l = 0; l < 8; l++) {
            float pv = Erow[l] * u_k * vrow[l];
            ps[pk][pq + l] = pv;
            mypsum += pv;
        }
        #pragma unroll
        for (int it = 0; it < 2; it++) {
            int idx = tid + it * 256;
            int nn = idx >> 4, c4 = (idx & 15) * 4;
            float4 v = *(const float4*)(fb + (size_t)(n0 + nn) * CC + c4);
            *(float4*)&fs[nn][c4] = v;
        }
        __syncthreads();
        #pragma unroll
        for (int nn = 0; nn < 32; nn++) {
            float a[4], bb[4];
            #pragma unroll
            for (int i = 0; i < 4; i++) a[i] = ps[trK*4 + i][nn];
            *(float4*)bb = *(const float4*)&fs[nn][tcC*4];
            #pragma unroll
            for (int i = 0; i < 4; i++)
                #pragma unroll
                for (int j = 0; j < 4; j++) acc[i][j] += a[i]*bb[j];
        }
        __syncthreads();
    }

    psump[pk][tid & 3] = mypsum;
    __syncthreads();
    if (tid < 64)
        psum_s[tid] = (psump[tid][0] + psump[tid][1]) + (psump[tid][2] + psump[tid][3]);
    __syncthreads();

    float* out = g_vagg + (size_t)b * KK * CC + ch * 64;
    const float* ag = aggA + ch * 64;
    #pragma unroll
    for (int i = 0; i < 4; i++) {
        int k = trK*4 + i;
        float psv = psum_s[k];
        float v0[4];
        #pragma unroll
        for (int j = 0; j < 4; j++)
            v0[j] = acc[i][j] - psv * ag[(size_t)k * CC + tcC*4 + j];
        *(float4*)(out + (size_t)k * CC + tcC*4) = *(float4*)v0;
    }
}

// ================= 9) final concat + l2norm =================
__global__ __launch_bounds__(256) void k_out(float* __restrict__ out)
{
    int b = blockIdx.x, tid = threadIdx.x;
    const float* t  = g_t + (size_t)b * DD;
    const float* vg = g_vagg + (size_t)b * KK * CC;
    float ss = 0.f;
    #pragma unroll
    for (int it = 0; it < 33; it++) {
        int i = tid + it * 256;
        float v = (i < DD) ? t[i] : vg[i - DD];
        ss += v * v;
    }
    __shared__ float red[8];
    ss = warpSum(ss);
    if ((tid & 31) == 0) red[tid >> 5] = ss;
    __syncthreads();
    float tot = 0.f;
    #pragma unroll
    for (int i = 0; i < 8; i++) tot += red[i];
    float inv = 1.0f / fmaxf(sqrtf(tot), 1e-12f);
    float* o = out + (size_t)b * OUTD;
    #pragma unroll
    for (int it = 0; it < 33; it++) {
        int i = tid + it * 256;
        float v = (i < DD) ? t[i] : vg[i - DD];
        o[i] = v * inv;
    }
}

// ================= launch =================
extern "C" void kernel_launch(void* const* d_in, const int* in_sizes, int n_in,
                              void* d_out, int out_size)
{
    (void)in_sizes; (void)n_in; (void)out_size;
    const float* x    = (const float*)d_in[0];
    const float* fw   = (const float*)d_in[1];
    const float* fb   = (const float*)d_in[2];
    const float* tw   = (const float*)d_in[3];
    const float* tb   = (const float*)d_in[4];
    const float* sa   = (const float*)d_in[5];
    const float* agg  = (const float*)d_in[6];
    const float* dust = (const float*)d_in[7];
    const float* lsh  = (const float*)d_in[8];
    float* out = (float*)d_out;

    static cudaStream_t s2 = nullptr;
    static cudaEvent_t eFork = nullptr, eJoin = nullptr;
    if (!s2) {
        cudaStreamCreateWithFlags(&s2, cudaStreamNonBlocking);
        cudaEventCreateWithFlags(&eFork, cudaEventDisableTiming);
        cudaEventCreateWithFlags(&eJoin, cudaEventDisableTiming);
    }

    // fork: k_f (feeds only k_agg) runs concurrently with k_s + Sinkhorn
    cudaEventRecord(eFork, 0);
    cudaStreamWaitEvent(s2, eFork, 0);
    k_f<<<(BB*NF)/128, 256, 0, s2>>>(x, fw, fb);
    cudaEventRecord(eJoin, s2);

    k_norms<<<8, 256>>>(sa);
    k_token<<<BB, 256>>>(x, tw, tb);
    k_init<<<(BB*NF)/256, 256>>>(dust);
    k_s<<<dim3(NF/256, BB), 256>>>(x, lsh);
    for (int it = 0; it < NITER; it++) {
        k_u<<<BB*KA, 192>>>();
        k_v<<<dim3(3, BB), 192>>>();
    }
    cudaStreamWaitEvent(0, eJoin, 0);
    k_agg<<<dim3(2, BB), 256>>>(agg);
    k_out<<<BB, 256>>>(out);
}

// round 8
// speedup vs baseline: 1.2950x; 1.0619x over previous
#include <cuda_runtime.h>
#include <math_constants.h>

// ---------------- problem constants ----------------
#define BB    64      // batch
#define NTOK  2305    // tokens incl. global token
#define NF    2304    // feature tokens (N-1)
#define DD    256     // channel dim
#define CC    128     // CLUSTER_DIM
#define KK    64      // NUM_CLUSTERS
#define KA    65      // K+1 (with dustbin)
#define NITER 5
#define OUTD  (DD + KK*CC)   // 8448

#define EXP_LOG_A (1.0f/65.0f)      // exp(-log(65))
#define EXP_LOG_B (1.0f/2304.0f)    // exp(-log(2304))

// ---------------- scratch (device globals; no allocs allowed) ----------------
__device__ float g_M[(size_t)BB*KA*NF];       // 38.3 MB  E = exp(s_aug / reg)
__device__ float g_eu[BB*KA];                 // exp(u)
__device__ float g_ev[BB*NF];                 // exp(v)
__device__ float g_t[BB*DD];
__device__ float g_G[(size_t)BB*KK*DD];       // 4.2 MB   G = p @ fi
__device__ float g_psum[BB*KK];
__device__ float g_vagg[(size_t)BB*KK*CC];    // 2 MB
__device__ float g_sanorm[KK*DD];

// ---------------- helpers ----------------
__device__ __forceinline__ float warpSum(float v){
    #pragma unroll
    for (int o = 16; o; o >>= 1) v += __shfl_xor_sync(0xffffffffu, v, o);
    return v;
}

// ================= 1) sa_norm =================
__global__ __launch_bounds__(256) void k_norms(const float* __restrict__ sa)
{
    int warp = threadIdx.x >> 5;
    int lane = threadIdx.x & 31;
    int row = blockIdx.x * 8 + warp;
    if (row >= 64) return;
    const float4* p = (const float4*)(sa + (size_t)row * DD);
    float4 a = p[lane], b = p[lane + 32];
    float ss = a.x*a.x + a.y*a.y + a.z*a.z + a.w*a.w
             + b.x*b.x + b.y*b.y + b.z*b.z + b.w*b.w;
    ss = warpSum(ss);
    float inv = 1.0f / fmaxf(sqrtf(ss), 1e-12f);
    float4* d = (float4*)(g_sanorm + (size_t)row * DD);
    a.x*=inv; a.y*=inv; a.z*=inv; a.w*=inv;
    b.x*=inv; b.y*=inv; b.z*=inv; b.w*=inv;
    d[lane] = a; d[lane + 32] = b;
}

// ================= 2) token projection =================
__global__ __launch_bounds__(256) void k_token(const float* __restrict__ x,
                                               const float* __restrict__ tw,
                                               const float* __restrict__ tb)
{
    int b = blockIdx.x, j = threadIdx.x;
    __shared__ float4 xs[64];
    if (j < 64) xs[j] = ((const float4*)(x + (size_t)b * NTOK * DD))[j];
    __syncthreads();
    const float4* w4 = (const float4*)(tw + (size_t)j * DD);
    float acc = tb[j];
    #pragma unroll 8
    for (int d = 0; d < 64; d++) {
        float4 wv = w4[d]; float4 xv = xs[d];
        acc += wv.x*xv.x + wv.y*xv.y + wv.z*xv.z + wv.w*xv.w;
    }
    g_t[b * DD + j] = acc;
}

// ================= 3) score GEMM + fused fi-norm + exp:
// E[b,k,n] = exp( (sa_n . fi_n) / ||fi_n|| * sharp / reg )
__global__ __launch_bounds__(256, 2) void k_s(const float* __restrict__ x,
                                              const float* __restrict__ lsh)
{
    int n0 = blockIdx.x * 256;     // 9 tiles
    int b  = blockIdx.y;
    float scale = __expf(lsh[0]) * 10.0f;

    __shared__ float As[2][16][68];
    __shared__ float Bs[2][16][260];
    __shared__ float sspart[256][4];

    int tid = threadIdx.x;
    int trK = tid >> 5;
    int tcN = tid & 31;
    float acc[8][8];
    #pragma unroll
    for (int i = 0; i < 8; i++)
        #pragma unroll
        for (int j = 0; j < 8; j++) acc[i][j] = 0.f;
    float ssl[4] = {0.f, 0.f, 0.f, 0.f};

    const float* fib = x + ((size_t)b * NTOK + 1 + n0) * DD;
    int kA = tid >> 2, dA = (tid & 3) * 4;

    // preload chunk 0
    {
        float4 v = *(const float4*)(g_sanorm + (size_t)kA * DD + dA);
        As[0][dA+0][kA] = v.x; As[0][dA+1][kA] = v.y;
        As[0][dA+2][kA] = v.z; As[0][dA+3][kA] = v.w;
        #pragma unroll
        for (int it = 0; it < 4; it++) {
            int idx = tid + it * 256;
            int n = idx >> 2, c4 = (idx & 3) * 4;
            float4 u = *(const float4*)(fib + (size_t)n * DD + c4);
            ssl[it] += u.x*u.x + u.y*u.y + u.z*u.z + u.w*u.w;
            Bs[0][c4+0][n] = u.x; Bs[0][c4+1][n] = u.y;
            Bs[0][c4+2][n] = u.z; Bs[0][c4+3][n] = u.w;
        }
    }
    __syncthreads();

    int buf = 0;
    for (int d0 = 16; d0 <= DD; d0 += 16) {
        float4 ra; float4 rb[4];
        if (d0 < DD) {
            ra = *(const float4*)(g_sanorm + (size_t)kA * DD + d0 + dA);
            #pragma unroll
            for (int it = 0; it < 4; it++) {
                int idx = tid + it * 256;
                int n = idx >> 2, c4 = (idx & 3) * 4;
                rb[it] = *(const float4*)(fib + (size_t)n * DD + d0 + c4);
                ssl[it] += rb[it].x*rb[it].x + rb[it].y*rb[it].y
                         + rb[it].z*rb[it].z + rb[it].w*rb[it].w;
            }
        }
        #pragma unroll
        for (int d = 0; d < 16; d++) {
            float a[8], bb[8];
            *(float4*)(a)    = *(const float4*)&As[buf][d][trK*8];
            *(float4*)(a+4)  = *(const float4*)&As[buf][d][trK*8+4];
            *(float4*)(bb)   = *(const float4*)&Bs[buf][d][tcN*8];
            *(float4*)(bb+4) = *(const float4*)&Bs[buf][d][tcN*8+4];
            #pragma unroll
            for (int i = 0; i < 8; i++)
                #pragma unroll
                for (int j = 0; j < 8; j++) acc[i][j] += a[i]*bb[j];
        }
        if (d0 < DD) {
            int nb = buf ^ 1;
            As[nb][dA+0][kA] = ra.x; As[nb][dA+1][kA] = ra.y;
            As[nb][dA+2][kA] = ra.z; As[nb][dA+3][kA] = ra.w;
            #pragma unroll
            for (int it = 0; it < 4; it++) {
                int idx = tid + it * 256;
                int n = idx >> 2, c4 = (idx & 3) * 4;
                Bs[nb][c4+0][n] = rb[it].x; Bs[nb][c4+1][n] = rb[it].y;
                Bs[nb][c4+2][n] = rb[it].z; Bs[nb][c4+3][n] = rb[it].w;
            }
            __syncthreads();
            buf = nb;
        }
    }

    // exchange sum-of-squares partials
    #pragma unroll
    for (int it = 0; it < 4; it++)
        sspart[(tid >> 2) + it * 64][tid & 3] = ssl[it];
    __syncthreads();

    float invs[8];
    #pragma unroll
    for (int j = 0; j < 8; j++) {
        float4 sv = *(const float4*)&sspart[tcN*8 + j][0];
        float ss = (sv.x + sv.y) + (sv.z + sv.w);
        invs[j] = scale / fmaxf(sqrtf(ss), 1e-12f);
    }
    #pragma unroll
    for (int i = 0; i < 8; i++) {
        int k = trK*8 + i;
        float v0[8];
        #pragma unroll
        for (int j = 0; j < 8; j++) v0[j] = __expf(acc[i][j] * invs[j]);
        float* dst = g_M + ((size_t)b * KA + k) * NF + n0 + tcN*8;
        *(float4*)dst       = *(float4*)(v0);
        *(float4*)(dst + 4) = *(float4*)(v0 + 4);
    }
}

// ================= 4) init: ev = 1, dustbin row E = exp(dust/reg) =================
__global__ __launch_bounds__(256) void k_init(const float* __restrict__ dust)
{
    int i = blockIdx.x * 256 + threadIdx.x;
    if (i < BB * NF) {
        g_ev[i] = 1.0f;
        int b = i / NF, n = i % NF;
        g_M[((size_t)b * KA + KK) * NF + n] = __expf(dust[0] * 10.0f);
    }
}

// ================= 5) Sinkhorn u-update: eu = (1/65) / sum_n E*ev =================
__global__ __launch_bounds__(192) void k_u()
{
    int bk = blockIdx.x;              // B*KA = 4160
    int b  = bk / KA;
    const float4* E  = (const float4*)(g_M + (size_t)bk * NF);
    const float4* ev = (const float4*)(g_ev + (size_t)b * NF);
    int tid = threadIdx.x;
    float s = 0.f;
    #pragma unroll
    for (int it = 0; it < 3; it++) {
        int i = tid + it * 192;
        float4 e = E[i], w = ev[i];
        s += e.x*w.x + e.y*w.y + e.z*w.z + e.w*w.w;
    }
    s = warpSum(s);
    __shared__ float red[6];
    if ((tid & 31) == 0) red[tid >> 5] = s;
    __syncthreads();
    if (tid == 0) {
        float t = ((red[0]+red[1]) + (red[2]+red[3])) + (red[4]+red[5]);
        g_eu[bk] = __fdividef(EXP_LOG_A, t);
    }
}

// ================= 6) Sinkhorn v-update: ev = (1/2304) / sum_k E*eu =================
__global__ __launch_bounds__(192) void k_v()
{
    int b  = blockIdx.y;
    int n4 = blockIdx.x * 192 + threadIdx.x;   // float4 index (grid.x=3)
    __shared__ float eus[KA];
    if (threadIdx.x < KA) eus[threadIdx.x] = g_eu[b * KA + threadIdx.x];
    __syncthreads();
    const float4* Eb = (const float4*)(g_M + (size_t)b * KA * NF);
    float4 acc = {0.f, 0.f, 0.f, 0.f};
    #pragma unroll 5
    for (int k = 0; k < KA; k++) {
        float4 e = Eb[(size_t)k * (NF/4) + n4];
        float u = eus[k];
        acc.x += e.x * u; acc.y += e.y * u;
        acc.z += e.z * u; acc.w += e.w * u;
    }
    float4 r;
    r.x = __fdividef(EXP_LOG_B, acc.x);
    r.y = __fdividef(EXP_LOG_B, acc.y);
    r.z = __fdividef(EXP_LOG_B, acc.z);
    r.w = __fdividef(EXP_LOG_B, acc.w);
    ((float4*)(g_ev + (size_t)b * NF))[n4] = r;
}

// ================= 7) G = p @ fi  (+ psum), p = eu*E*ev =================
// grid (2, B): ch selects d-half (128 of 256). 64(k) x 128(d) output per block.
__global__ __launch_bounds__(256) void k_pg(const float* __restrict__ x)
{
    int ch = blockIdx.x;
    int b  = blockIdx.y;
    __shared__ float ps[64][33];      // p tile [k][nn]
    __shared__ float fs[32][132];     // fi tile [nn][d]
    __shared__ float uc[64];
    __shared__ float psump[64][4];

    int tid = threadIdx.x;
    if (tid < 64) uc[tid] = g_eu[b * KA + tid];
    __syncthreads();

    int pk = tid >> 2;
    int pq = (tid & 3) * 8;
    int trK = tid >> 4, tcC = tid & 15;
    float acc[4][8];
    #pragma unroll
    for (int i = 0; i < 4; i++)
        #pragma unroll
        for (int j = 0; j < 8; j++) acc[i][j] = 0.f;
    float mypsum = 0.f;

    const float* Eb = g_M + (size_t)b * KA * NF;
    const float* vb = g_ev + (size_t)b * NF;
    const float* xb = x + ((size_t)b * NTOK + 1) * DD + ch * 128;
    float u_k = uc[pk];

    for (int n0 = 0; n0 < NF; n0 += 32) {
        const float* Erow = Eb + (size_t)pk * NF + n0 + pq;
        const float* vrow = vb + n0 + pq;
        #pragma unroll
        for (int l = 0; l < 8; l++) {
            float pv = Erow[l] * u_k * vrow[l];
            ps[pk][pq + l] = pv;
            mypsum += pv;
        }
        #pragma unroll
        for (int it = 0; it < 4; it++) {      // 32 rows x 128 floats = 1024 float4
            int idx = tid + it * 256;
            int nn = idx >> 5, c4 = (idx & 31) * 4;
            float4 v = *(const float4*)(xb + (size_t)(n0 + nn) * DD + c4);
            *(float4*)&fs[nn][c4] = v;
        }
        __syncthreads();
        #pragma unroll
        for (int nn = 0; nn < 32; nn++) {
            float a[4], bb[8];
            #pragma unroll
            for (int i = 0; i < 4; i++) a[i] = ps[trK*4 + i][nn];
            *(float4*)(bb)   = *(const float4*)&fs[nn][tcC*8];
            *(float4*)(bb+4) = *(const float4*)&fs[nn][tcC*8+4];
            #pragma unroll
            for (int i = 0; i < 4; i++)
                #pragma unroll
                for (int j = 0; j < 8; j++) acc[i][j] += a[i]*bb[j];
        }
        __syncthreads();
    }

    psump[pk][tid & 3] = mypsum;
    __syncthreads();
    if (ch == 0 && tid < 64)
        g_psum[b * KK + tid] = (psump[tid][0] + psump[tid][1])
                             + (psump[tid][2] + psump[tid][3]);

    float* out = g_G + ((size_t)b * KK) * DD + ch * 128;
    #pragma unroll
    for (int i = 0; i < 4; i++) {
        int k = trK*4 + i;
        float* dst = out + (size_t)k * DD + tcC*8;
        *(float4*)dst       = *(float4*)(acc[i]);
        *(float4*)(dst + 4) = *(float4*)(acc[i] + 4);
    }
}

// ================= 8) v_agg = G @ Wf^T + psum*(bias - agg) =================
// one block per batch: 64(k) x 128(c), K = 256(d)
__global__ __launch_bounds__(256) void k_vagg(const float* __restrict__ w,
                                              const float* __restrict__ bias,
                                              const float* __restrict__ aggA)
{
    int b = blockIdx.x;
    __shared__ float Gs[32][68];    // [d][k]
    __shared__ float Ws[32][132];   // [d][c]
    int tid = threadIdx.x;
    int trK = tid >> 4, tcC = tid & 15;
    float acc[4][8];
    #pragma unroll
    for (int i = 0; i < 4; i++)
        #pragma unroll
        for (int j = 0; j < 8; j++) acc[i][j] = 0.f;

    const float* Gb = g_G + (size_t)b * KK * DD;

    for (int d0 = 0; d0 < DD; d0 += 32) {
        #pragma unroll
        for (int it = 0; it < 2; it++) {     // 64x32 G tile
            int idx = tid + it * 256;
            int k = idx >> 3, d4 = (idx & 7) * 4;
            float4 v = *(const float4*)(Gb + (size_t)k * DD + d0 + d4);
            Gs[d4+0][k] = v.x; Gs[d4+1][k] = v.y;
            Gs[d4+2][k] = v.z; Gs[d4+3][k] = v.w;
        }
        #pragma unroll
        for (int it = 0; it < 4; it++) {     // 128x32 W tile
            int idx = tid + it * 256;
            int c = idx >> 3, d4 = (idx & 7) * 4;
            float4 v = *(const float4*)(w + (size_t)c * DD + d0 + d4);
            Ws[d4+0][c] = v.x; Ws[d4+1][c] = v.y;
            Ws[d4+2][c] = v.z; Ws[d4+3][c] = v.w;
        }
        __syncthreads();
        #pragma unroll
        for (int d = 0; d < 32; d++) {
            float a[4], bb[8];
            #pragma unroll
            for (int i = 0; i < 4; i++) a[i] = Gs[d][trK*4 + i];
            *(float4*)(bb)   = *(const float4*)&Ws[d][tcC*8];
            *(float4*)(bb+4) = *(const float4*)&Ws[d][tcC*8+4];
            #pragma unroll
            for (int i = 0; i < 4; i++)
                #pragma unroll
                for (int j = 0; j < 8; j++) acc[i][j] += a[i]*bb[j];
        }
        __syncthreads();
    }

    float bi[8];
    *(float4*)(bi)   = *(const float4*)(bias + tcC*8);
    *(float4*)(bi+4) = *(const float4*)(bias + tcC*8 + 4);
    float* out = g_vagg + (size_t)b * KK * CC;
    #pragma unroll
    for (int i = 0; i < 4; i++) {
        int k = trK*4 + i;
        float psv = g_psum[b * KK + k];
        float v0[8];
        #pragma unroll
        for (int j = 0; j < 8; j++)
            v0[j] = acc[i][j] + psv * (bi[j] - aggA[(size_t)k * CC + tcC*8 + j]);
        float* dst = out + (size_t)k * CC + tcC*8;
        *(float4*)dst       = *(float4*)(v0);
        *(float4*)(dst + 4) = *(float4*)(v0 + 4);
    }
}

// ================= 9) final concat + l2norm =================
__global__ __launch_bounds__(256) void k_out(float* __restrict__ out)
{
    int b = blockIdx.x, tid = threadIdx.x;
    const float* t  = g_t + (size_t)b * DD;
    const float* vg = g_vagg + (size_t)b * KK * CC;
    float ss = 0.f;
    #pragma unroll
    for (int it = 0; it < 33; it++) {
        int i = tid + it * 256;
        float v = (i < DD) ? t[i] : vg[i - DD];
        ss += v * v;
    }
    __shared__ float red[8];
    ss = warpSum(ss);
    if ((tid & 31) == 0) red[tid >> 5] = ss;
    __syncthreads();
    float tot = 0.f;
    #pragma unroll
    for (int i = 0; i < 8; i++) tot += red[i];
    float inv = 1.0f / fmaxf(sqrtf(tot), 1e-12f);
    float* o = out + (size_t)b * OUTD;
    #pragma unroll
    for (int it = 0; it < 33; it++) {
        int i = tid + it * 256;
        float v = (i < DD) ? t[i] : vg[i - DD];
        o[i] = v * inv;
    }
}

// ================= launch =================
extern "C" void kernel_launch(void* const* d_in, const int* in_sizes, int n_in,
                              void* d_out, int out_size)
{
    (void)in_sizes; (void)n_in; (void)out_size;
    const float* x    = (const float*)d_in[0];
    const float* fw   = (const float*)d_in[1];
    const float* fb   = (const float*)d_in[2];
    const float* tw   = (const float*)d_in[3];
    const float* tb   = (const float*)d_in[4];
    const float* sa   = (const float*)d_in[5];
    const float* agg  = (const float*)d_in[6];
    const float* dust = (const float*)d_in[7];
    const float* lsh  = (const float*)d_in[8];
    float* out = (float*)d_out;

    k_norms<<<8, 256>>>(sa);
    k_token<<<BB, 256>>>(x, tw, tb);
    k_init<<<(BB*NF)/256, 256>>>(dust);
    k_s<<<dim3(NF/256, BB), 256>>>(x, lsh);
    for (int it = 0; it < NITER; it++) {
        k_u<<<BB*KA, 192>>>();
        k_v<<<dim3(3, BB), 192>>>();
    }
    k_pg<<<dim3(2, BB), 256>>>(x);
    k_vagg<<<BB, 256>>>(fw, fb, agg);
    k_out<<<BB, 256>>>(out);
}

// round 9
// speedup vs baseline: 1.7801x; 1.3746x over previous
#include <cuda_runtime.h>
#include <math_constants.h>

// ---------------- problem constants ----------------
#define BB    64      // batch
#define NTOK  2305    // tokens incl. global token
#define NF    2304    // feature tokens (N-1)
#define DD    256     // channel dim
#define CC    128     // CLUSTER_DIM
#define KK    64      // NUM_CLUSTERS
#define KA    65      // K+1 (with dustbin)
#define NITER 5
#define OUTD  (DD + KK*CC)   // 8448
#define QSP   4              // n-splits for k_pg
#define NQ    (NF/QSP)       // 576

#define EXP_LOG_A (1.0f/65.0f)      // exp(-log(65))
#define EXP_LOG_B (1.0f/2304.0f)    // exp(-log(2304))

// ---------------- scratch (device globals; no allocs allowed) ----------------
__device__ float g_M[(size_t)BB*KK*NF];        // 37.7 MB  E = exp(s/reg), 64 rows (no dustbin)
__device__ float g_eu[BB*KA];                  // eu[0..63]; [64] = A/sum(ev) (pre-multiplied dust term)
__device__ float g_ev[BB*NF];
__device__ float g_sevp[BB*3];                 // per-k_v-block partial sums of ev
__device__ float g_t[BB*DD];
__device__ float g_G[(size_t)QSP*BB*KK*DD];    // 16.8 MB  partial G = p @ fi
__device__ float g_psum[QSP*BB*KK];
__device__ float g_vagg[(size_t)BB*KK*CC];
__device__ float g_sanorm[KK*DD];

// ---------------- helpers ----------------
__device__ __forceinline__ float warpSum(float v){
    #pragma unroll
    for (int o = 16; o; o >>= 1) v += __shfl_xor_sync(0xffffffffu, v, o);
    return v;
}

// packed-fp32 FMA: d.{lo,hi} += a.{lo,hi} * b.{lo,hi}
#define FMA2(d, a, b) asm("fma.rn.f32x2 %0, %1, %2, %0;" : "+l"(d) : "l"(a), "l"(b))
#define PACK2(d, s)   asm("mov.b64 %0, {%1, %1};" : "=l"(d) : "r"(s))
__device__ __forceinline__ float2 u2f(unsigned long long v){
    float2 r;
    asm("mov.b64 {%0, %1}, %2;" : "=f"(r.x), "=f"(r.y) : "l"(v));
    return r;
}

// ================= 1) sa_norm =================
__global__ __launch_bounds__(256) void k_norms(const float* __restrict__ sa)
{
    int warp = threadIdx.x >> 5;
    int lane = threadIdx.x & 31;
    int row = blockIdx.x * 8 + warp;
    if (row >= 64) return;
    const float4* p = (const float4*)(sa + (size_t)row * DD);
    float4 a = p[lane], b = p[lane + 32];
    float ss = a.x*a.x + a.y*a.y + a.z*a.z + a.w*a.w
             + b.x*b.x + b.y*b.y + b.z*b.z + b.w*b.w;
    ss = warpSum(ss);
    float inv = 1.0f / fmaxf(sqrtf(ss), 1e-12f);
    float4* d = (float4*)(g_sanorm + (size_t)row * DD);
    a.x*=inv; a.y*=inv; a.z*=inv; a.w*=inv;
    b.x*=inv; b.y*=inv; b.z*=inv; b.w*=inv;
    d[lane] = a; d[lane + 32] = b;
}

// ================= 2) token projection =================
__global__ __launch_bounds__(256) void k_token(const float* __restrict__ x,
                                               const float* __restrict__ tw,
                                               const float* __restrict__ tb)
{
    int b = blockIdx.x, j = threadIdx.x;
    __shared__ float4 xs[64];
    if (j < 64) xs[j] = ((const float4*)(x + (size_t)b * NTOK * DD))[j];
    __syncthreads();
    const float4* w4 = (const float4*)(tw + (size_t)j * DD);
    float acc = tb[j];
    #pragma unroll 8
    for (int d = 0; d < 64; d++) {
        float4 wv = w4[d]; float4 xv = xs[d];
        acc += wv.x*xv.x + wv.y*xv.y + wv.z*xv.z + wv.w*xv.w;
    }
    g_t[b * DD + j] = acc;
}

// ================= 3) score GEMM (FFMA2) + fused fi-norm + exp =================
__global__ __launch_bounds__(256, 2) void k_s(const float* __restrict__ x,
                                              const float* __restrict__ lsh)
{
    int n0 = blockIdx.x * 256;     // 9 tiles
    int b  = blockIdx.y;
    float scale = __expf(lsh[0]) * 10.0f;

    __shared__ float As[2][16][68];
    __shared__ float Bs[2][16][260];
    __shared__ float sspart[256][4];

    int tid = threadIdx.x;
    int trK = tid >> 5;
    int tcN = tid & 31;
    unsigned long long acc2[8][4];
    #pragma unroll
    for (int i = 0; i < 8; i++)
        #pragma unroll
        for (int j = 0; j < 4; j++) acc2[i][j] = 0ull;
    float ssl[4] = {0.f, 0.f, 0.f, 0.f};

    const float* fib = x + ((size_t)b * NTOK + 1 + n0) * DD;
    int kA = tid >> 2, dA = (tid & 3) * 4;

    // preload chunk 0
    {
        float4 v = *(const float4*)(g_sanorm + (size_t)kA * DD + dA);
        As[0][dA+0][kA] = v.x; As[0][dA+1][kA] = v.y;
        As[0][dA+2][kA] = v.z; As[0][dA+3][kA] = v.w;
        #pragma unroll
        for (int it = 0; it < 4; it++) {
            int idx = tid + it * 256;
            int n = idx >> 2, c4 = (idx & 3) * 4;
            float4 u = *(const float4*)(fib + (size_t)n * DD + c4);
            ssl[it] += u.x*u.x + u.y*u.y + u.z*u.z + u.w*u.w;
            Bs[0][c4+0][n] = u.x; Bs[0][c4+1][n] = u.y;
            Bs[0][c4+2][n] = u.z; Bs[0][c4+3][n] = u.w;
        }
    }
    __syncthreads();

    int buf = 0;
    for (int d0 = 16; d0 <= DD; d0 += 16) {
        float4 ra; float4 rb[4];
        if (d0 < DD) {
            ra = *(const float4*)(g_sanorm + (size_t)kA * DD + d0 + dA);
            #pragma unroll
            for (int it = 0; it < 4; it++) {
                int idx = tid + it * 256;
                int n = idx >> 2, c4 = (idx & 3) * 4;
                rb[it] = *(const float4*)(fib + (size_t)n * DD + d0 + c4);
                ssl[it] += rb[it].x*rb[it].x + rb[it].y*rb[it].y
                         + rb[it].z*rb[it].z + rb[it].w*rb[it].w;
            }
        }
        #pragma unroll
        for (int d = 0; d < 16; d++) {
            uint4 av0 = *(const uint4*)&As[buf][d][trK*8];
            uint4 av1 = *(const uint4*)&As[buf][d][trK*8+4];
            ulonglong2 bb0 = *(const ulonglong2*)&Bs[buf][d][tcN*8];
            ulonglong2 bb1 = *(const ulonglong2*)&Bs[buf][d][tcN*8+4];
            unsigned long long a2;
            PACK2(a2, av0.x);
            FMA2(acc2[0][0], a2, bb0.x); FMA2(acc2[0][1], a2, bb0.y);
            FMA2(acc2[0][2], a2, bb1.x); FMA2(acc2[0][3], a2, bb1.y);
            PACK2(a2, av0.y);
            FMA2(acc2[1][0], a2, bb0.x); FMA2(acc2[1][1], a2, bb0.y);
            FMA2(acc2[1][2], a2, bb1.x); FMA2(acc2[1][3], a2, bb1.y);
            PACK2(a2, av0.z);
            FMA2(acc2[2][0], a2, bb0.x); FMA2(acc2[2][1], a2, bb0.y);
            FMA2(acc2[2][2], a2, bb1.x); FMA2(acc2[2][3], a2, bb1.y);
            PACK2(a2, av0.w);
            FMA2(acc2[3][0], a2, bb0.x); FMA2(acc2[3][1], a2, bb0.y);
            FMA2(acc2[3][2], a2, bb1.x); FMA2(acc2[3][3], a2, bb1.y);
            PACK2(a2, av1.x);
            FMA2(acc2[4][0], a2, bb0.x); FMA2(acc2[4][1], a2, bb0.y);
            FMA2(acc2[4][2], a2, bb1.x); FMA2(acc2[4][3], a2, bb1.y);
            PACK2(a2, av1.y);
            FMA2(acc2[5][0], a2, bb0.x); FMA2(acc2[5][1], a2, bb0.y);
            FMA2(acc2[5][2], a2, bb1.x); FMA2(acc2[5][3], a2, bb1.y);
            PACK2(a2, av1.z);
            FMA2(acc2[6][0], a2, bb0.x); FMA2(acc2[6][1], a2, bb0.y);
            FMA2(acc2[6][2], a2, bb1.x); FMA2(acc2[6][3], a2, bb1.y);
            PACK2(a2, av1.w);
            FMA2(acc2[7][0], a2, bb0.x); FMA2(acc2[7][1], a2, bb0.y);
            FMA2(acc2[7][2], a2, bb1.x); FMA2(acc2[7][3], a2, bb1.y);
        }
        if (d0 < DD) {
            int nb = buf ^ 1;
            As[nb][dA+0][kA] = ra.x; As[nb][dA+1][kA] = ra.y;
            As[nb][dA+2][kA] = ra.z; As[nb][dA+3][kA] = ra.w;
            #pragma unroll
            for (int it = 0; it < 4; it++) {
                int idx = tid + it * 256;
                int n = idx >> 2, c4 = (idx & 3) * 4;
                Bs[nb][c4+0][n] = rb[it].x; Bs[nb][c4+1][n] = rb[it].y;
                Bs[nb][c4+2][n] = rb[it].z; Bs[nb][c4+3][n] = rb[it].w;
            }
            __syncthreads();
            buf = nb;
        }
    }

    // exchange sum-of-squares partials
    #pragma unroll
    for (int it = 0; it < 4; it++)
        sspart[(tid >> 2) + it * 64][tid & 3] = ssl[it];
    __syncthreads();

    float invs[8];
    #pragma unroll
    for (int j = 0; j < 8; j++) {
        float4 sv = *(const float4*)&sspart[tcN*8 + j][0];
        float ss = (sv.x + sv.y) + (sv.z + sv.w);
        invs[j] = scale / fmaxf(sqrtf(ss), 1e-12f);
    }
    #pragma unroll
    for (int i = 0; i < 8; i++) {
        int k = trK*8 + i;
        float v0[8];
        #pragma unroll
        for (int j2 = 0; j2 < 4; j2++) {
            float2 p = u2f(acc2[i][j2]);
            v0[2*j2]   = __expf(p.x * invs[2*j2]);
            v0[2*j2+1] = __expf(p.y * invs[2*j2+1]);
        }
        float* dst = g_M + ((size_t)b * KK + k) * NF + n0 + tcN*8;
        *(float4*)dst       = *(float4*)(v0);
        *(float4*)(dst + 4) = *(float4*)(v0 + 4);
    }
}

// ================= 4) init: ev = 1, sevp partials = 768 =================
__global__ __launch_bounds__(256) void k_init()
{
    int i = blockIdx.x * 256 + threadIdx.x;
    if (i < BB * NF) g_ev[i] = 1.0f;
    if (i < BB * 3)  g_sevp[i] = (float)(NF / 3);
}

// ================= 5) Sinkhorn u-update =================
// k<64: eu = A / sum_n E*ev.  k==64 (dustbin, analytic): g_eu[..64] = A / sum(ev).
__global__ __launch_bounds__(192) void k_u()
{
    int bk = blockIdx.x;              // B*KA = 4160
    int b  = bk / KA, k = bk % KA;
    if (k == KK) {
        if (threadIdx.x == 0) {
            float sev = g_sevp[b*3+0] + g_sevp[b*3+1] + g_sevp[b*3+2];
            g_eu[b * KA + KK] = __fdividef(EXP_LOG_A, sev);
        }
        return;
    }
    const float4* E  = (const float4*)(g_M + ((size_t)b * KK + k) * NF);
    const float4* ev = (const float4*)(g_ev + (size_t)b * NF);
    int tid = threadIdx.x;
    float s = 0.f;
    #pragma unroll
    for (int it = 0; it < 3; it++) {
        int i = tid + it * 192;
        float4 e = E[i], w = ev[i];
        s += e.x*w.x + e.y*w.y + e.z*w.z + e.w*w.w;
    }
    s = warpSum(s);
    __shared__ float red[6];
    if ((tid & 31) == 0) red[tid >> 5] = s;
    __syncthreads();
    if (tid == 0) {
        float t = ((red[0]+red[1]) + (red[2]+red[3])) + (red[4]+red[5]);
        g_eu[b * KA + k] = __fdividef(EXP_LOG_A, t);
    }
}

// ================= 6) Sinkhorn v-update (+ Sum(ev) partials) =================
__global__ __launch_bounds__(192) void k_v()
{
    int b  = blockIdx.y;
    int n4 = blockIdx.x * 192 + threadIdx.x;   // float4 index (grid.x=3)
    __shared__ float eus[KA];
    __shared__ float red[6];
    int tid = threadIdx.x;
    if (tid < KA) eus[tid] = g_eu[b * KA + tid];
    __syncthreads();
    const float4* Eb = (const float4*)(g_M + (size_t)b * KK * NF);
    float dc = eus[KK];                  // = A / sum(ev)  (edust cancels exactly)
    float4 acc = {dc, dc, dc, dc};
    #pragma unroll 8
    for (int k = 0; k < KK; k++) {
        float4 e = Eb[(size_t)k * (NF/4) + n4];
        float u = eus[k];
        acc.x += e.x * u; acc.y += e.y * u;
        acc.z += e.z * u; acc.w += e.w * u;
    }
    float4 r;
    r.x = __fdividef(EXP_LOG_B, acc.x);
    r.y = __fdividef(EXP_LOG_B, acc.y);
    r.z = __fdividef(EXP_LOG_B, acc.z);
    r.w = __fdividef(EXP_LOG_B, acc.w);
    ((float4*)(g_ev + (size_t)b * NF))[n4] = r;

    float sp = (r.x + r.y) + (r.z + r.w);
    sp = warpSum(sp);
    if ((tid & 31) == 0) red[tid >> 5] = sp;
    __syncthreads();
    if (tid == 0)
        g_sevp[b*3 + blockIdx.x] = ((red[0]+red[1]) + (red[2]+red[3])) + (red[4]+red[5]);
}

// ================= 7) partial G = p @ fi (FFMA2), p = eu*E*ev =================
// grid (QSP, B): block handles n-range [q*576,(q+1)*576), full 64k x 256d output partial.
__global__ __launch_bounds__(256, 2) void k_pg(const float* __restrict__ x)
{
    int q = blockIdx.x;
    int b = blockIdx.y;
    __shared__ float ps[64][33];      // p tile [k][nn]
    __shared__ float fs[32][260];     // fi tile [nn][d] (full 256)
    __shared__ float uc[64];
    __shared__ float psump[64][4];

    int tid = threadIdx.x;
    if (tid < 64) uc[tid] = g_eu[b * KA + tid];
    __syncthreads();

    int pk = tid >> 2, pq = (tid & 3) * 8;
    int trK = tid >> 5, tcC = tid & 31;
    unsigned long long acc2[8][4];
    #pragma unroll
    for (int i = 0; i < 8; i++)
        #pragma unroll
        for (int j = 0; j < 4; j++) acc2[i][j] = 0ull;
    float mypsum = 0.f;

    const float* Eb = g_M + (size_t)b * KK * NF + q * NQ;
    const float* vb = g_ev + (size_t)b * NF + q * NQ;
    const float* xb = x + ((size_t)b * NTOK + 1 + q * NQ) * DD;
    float u_k = uc[pk];

    for (int n0 = 0; n0 < NQ; n0 += 32) {
        // p tile: 64 x 32
        {
            const float* Erow = Eb + (size_t)pk * NF + n0 + pq;
            const float* vrow = vb + n0 + pq;
            float4 e0 = *(const float4*)(Erow),   e1 = *(const float4*)(Erow + 4);
            float4 w0 = *(const float4*)(vrow),   w1 = *(const float4*)(vrow + 4);
            float pv[8];
            pv[0] = e0.x*u_k*w0.x; pv[1] = e0.y*u_k*w0.y;
            pv[2] = e0.z*u_k*w0.z; pv[3] = e0.w*u_k*w0.w;
            pv[4] = e1.x*u_k*w1.x; pv[5] = e1.y*u_k*w1.y;
            pv[6] = e1.z*u_k*w1.z; pv[7] = e1.w*u_k*w1.w;
            #pragma unroll
            for (int l = 0; l < 8; l++) { ps[pk][pq + l] = pv[l]; mypsum += pv[l]; }
        }
        // fi tile: 32 x 256 = 2048 float4
        #pragma unroll
        for (int it = 0; it < 8; it++) {
            int idx = tid + it * 256;
            int nn = idx >> 6, c4 = (idx & 63) * 4;
            float4 v = *(const float4*)(xb + (size_t)(n0 + nn) * DD + c4);
            *(float4*)&fs[nn][c4] = v;
        }
        __syncthreads();
        #pragma unroll
        for (int nn = 0; nn < 32; nn++) {
            ulonglong2 bb0 = *(const ulonglong2*)&fs[nn][tcC*8];
            ulonglong2 bb1 = *(const ulonglong2*)&fs[nn][tcC*8+4];
            #pragma unroll
            for (int i = 0; i < 8; i++) {
                unsigned long long a2;
                PACK2(a2, *(const unsigned*)&ps[trK*8 + i][nn]);
                FMA2(acc2[i][0], a2, bb0.x);
                FMA2(acc2[i][1], a2, bb0.y);
                FMA2(acc2[i][2], a2, bb1.x);
                FMA2(acc2[i][3], a2, bb1.y);
            }
        }
        __syncthreads();
    }

    psump[pk][tid & 3] = mypsum;
    __syncthreads();
    if (tid < 64)
        g_psum[((size_t)q * BB + b) * KK + tid] =
            (psump[tid][0] + psump[tid][1]) + (psump[tid][2] + psump[tid][3]);

    float* out = g_G + ((size_t)q * BB + b) * KK * DD;
    #pragma unroll
    for (int i = 0; i < 8; i++) {
        int k = trK*8 + i;
        float v0[8];
        #pragma unroll
        for (int j2 = 0; j2 < 4; j2++) {
            float2 p = u2f(acc2[i][j2]);
            v0[2*j2] = p.x; v0[2*j2+1] = p.y;
        }
        float* dst = out + (size_t)k * DD + tcC*8;
        *(float4*)dst       = *(float4*)(v0);
        *(float4*)(dst + 4) = *(float4*)(v0 + 4);
    }
}

// ================= 8) v_agg = (sum_q G) @ Wf^T + psum*(bias - agg) =================
__global__ __launch_bounds__(256) void k_vagg(const float* __restrict__ w,
                                              const float* __restrict__ bias,
                                              const float* __restrict__ aggA)
{
    int b = blockIdx.x;
    __shared__ float Gs[32][68];    // [d][k]
    __shared__ float Ws[32][132];   // [d][c]
    int tid = threadIdx.x;
    int trK = tid >> 4, tcC = tid & 15;
    float acc[4][8];
    #pragma unroll
    for (int i = 0; i < 4; i++)
        #pragma unroll
        for (int j = 0; j < 8; j++) acc[i][j] = 0.f;

    for (int d0 = 0; d0 < DD; d0 += 32) {
        #pragma unroll
        for (int it = 0; it < 2; it++) {     // 64x32 G tile (sum 4 partials)
            int idx = tid + it * 256;
            int k = idx >> 3, d4 = (idx & 7) * 4;
            float4 s = {0.f, 0.f, 0.f, 0.f};
            #pragma unroll
            for (int q = 0; q < QSP; q++) {
                float4 v = *(const float4*)(g_G + ((size_t)q * BB + b) * KK * DD
                                            + (size_t)k * DD + d0 + d4);
                s.x += v.x; s.y += v.y; s.z += v.z; s.w += v.w;
            }
            Gs[d4+0][k] = s.x; Gs[d4+1][k] = s.y;
            Gs[d4+2][k] = s.z; Gs[d4+3][k] = s.w;
        }
        #pragma unroll
        for (int it = 0; it < 4; it++) {     // 128x32 W tile
            int idx = tid + it * 256;
            int c = idx >> 3, d4 = (idx & 7) * 4;
            float4 v = *(const float4*)(w + (size_t)c * DD + d0 + d4);
            Ws[d4+0][c] = v.x; Ws[d4+1][c] = v.y;
            Ws[d4+2][c] = v.z; Ws[d4+3][c] = v.w;
        }
        __syncthreads();
        #pragma unroll
        for (int d = 0; d < 32; d++) {
            float a[4], bb[8];
            #pragma unroll
            for (int i = 0; i < 4; i++) a[i] = Gs[d][trK*4 + i];
            *(float4*)(bb)   = *(const float4*)&Ws[d][tcC*8];
            *(float4*)(bb+4) = *(const float4*)&Ws[d][tcC*8+4];
            #pragma unroll
            for (int i = 0; i < 4; i++)
                #pragma unroll
                for (int j = 0; j < 8; j++) acc[i][j] += a[i]*bb[j];
        }
        __syncthreads();
    }

    float bi[8];
    *(float4*)(bi)   = *(const float4*)(bias + tcC*8);
    *(float4*)(bi+4) = *(const float4*)(bias + tcC*8 + 4);
    float* out = g_vagg + (size_t)b * KK * CC;
    #pragma unroll
    for (int i = 0; i < 4; i++) {
        int k = trK*4 + i;
        float psv = 0.f;
        #pragma unroll
        for (int q = 0; q < QSP; q++)
            psv += g_psum[((size_t)q * BB + b) * KK + k];
        float v0[8];
        #pragma unroll
        for (int j = 0; j < 8; j++)
            v0[j] = acc[i][j] + psv * (bi[j] - aggA[(size_t)k * CC + tcC*8 + j]);
        float* dst = out + (size_t)k * CC + tcC*8;
        *(float4*)dst       = *(float4*)(v0);
        *(float4*)(dst + 4) = *(float4*)(v0 + 4);
    }
}

// ================= 9) final concat + l2norm =================
__global__ __launch_bounds__(256) void k_out(float* __restrict__ out)
{
    int b = blockIdx.x, tid = threadIdx.x;
    const float* t  = g_t + (size_t)b * DD;
    const float* vg = g_vagg + (size_t)b * KK * CC;
    float ss = 0.f;
    #pragma unroll
    for (int it = 0; it < 33; it++) {
        int i = tid + it * 256;
        float v = (i < DD) ? t[i] : vg[i - DD];
        ss += v * v;
    }
    __shared__ float red[8];
    ss = warpSum(ss);
    if ((tid & 31) == 0) red[tid >> 5] = ss;
    __syncthreads();
    float tot = 0.f;
    #pragma unroll
    for (int i = 0; i < 8; i++) tot += red[i];
    float inv = 1.0f / fmaxf(sqrtf(tot), 1e-12f);
    float* o = out + (size_t)b * OUTD;
    #pragma unroll
    for (int it = 0; it < 33; it++) {
        int i = tid + it * 256;
        float v = (i < DD) ? t[i] : vg[i - DD];
        o[i] = v * inv;
    }
}

// ================= launch =================
extern "C" void kernel_launch(void* const* d_in, const int* in_sizes, int n_in,
                              void* d_out, int out_size)
{
    (void)in_sizes; (void)n_in; (void)out_size;
    const float* x    = (const float*)d_in[0];
    const float* fw   = (const float*)d_in[1];
    const float* fb   = (const float*)d_in[2];
    const float* tw   = (const float*)d_in[3];
    const float* tb   = (const float*)d_in[4];
    const float* sa   = (const float*)d_in[5];
    const float* agg  = (const float*)d_in[6];
    const float* dust = (const float*)d_in[7];   // mathematically cancels (constant dustbin row)
    const float* lsh  = (const float*)d_in[8];
    (void)dust;
    float* out = (float*)d_out;

    k_norms<<<8, 256>>>(sa);
    k_token<<<BB, 256>>>(x, tw, tb);
    k_init<<<(BB*NF)/256, 256>>>();
    k_s<<<dim3(NF/256, BB), 256>>>(x, lsh);
    for (int it = 0; it < NITER; it++) {
        k_u<<<BB*KA, 192>>>();
        k_v<<<dim3(3, BB), 192>>>();
    }
    k_pg<<<dim3(QSP, BB), 256>>>(x);
    k_vagg<<<BB, 256>>>(fw, fb, agg);
    k_out<<<BB, 256>>>(out);
}

// round 11
// speedup vs baseline: 2.1236x; 1.1930x over previous
#include <cuda_runtime.h>
#include <cuda_bf16.h>
#include <math_constants.h>
#include <cstdint>

// ---------------- problem constants ----------------
#define BB    64      // batch
#define NTOK  2305    // tokens incl. global token
#define NF    2304    // feature tokens (N-1)
#define DD    256     // channel dim
#define CC    128     // CLUSTER_DIM
#define KK    64      // NUM_CLUSTERS
#define KA    65      // K+1 (with dustbin)
#define NITER 5
#define OUTD  (DD + KK*CC)   // 8448
#define QSP   4              // n-splits for k_pg
#define NQ    (NF/QSP)       // 576

#define EXP_LOG_A (1.0f/65.0f)
#define EXP_LOG_B (1.0f/2304.0f)

// ---------------- scratch (device globals; no allocs allowed) ----------------
__device__ float g_M[(size_t)BB*KK*NF];        // E = exp(s/reg)
__device__ float g_eu[BB*KA];
__device__ float g_ev[BB*NF];
__device__ float g_sevp[BB*3];
__device__ float g_t[BB*DD];
__device__ float g_G[(size_t)QSP*BB*KK*DD];
__device__ float g_psum[QSP*BB*KK];
__device__ float g_vagg[(size_t)BB*KK*CC];
__device__ __align__(16) __nv_bfloat16 g_sahi[KK*DD];   // sa_norm split: hi
__device__ __align__(16) __nv_bfloat16 g_salo[KK*DD];   //               lo

// ---------------- helpers ----------------
__device__ __forceinline__ float warpSum(float v){
    #pragma unroll
    for (int o = 16; o; o >>= 1) v += __shfl_xor_sync(0xffffffffu, v, o);
    return v;
}
#define FMA2(d, a, b) asm("fma.rn.f32x2 %0, %1, %2, %0;" : "+l"(d) : "l"(a), "l"(b))
#define PACK2(d, s)   asm("mov.b64 %0, {%1, %1};" : "=l"(d) : "r"(s))
__device__ __forceinline__ float2 u2f(unsigned long long v){
    float2 r;
    asm("mov.b64 {%0, %1}, %2;" : "=f"(r.x), "=f"(r.y) : "l"(v));
    return r;
}

// warp MMA: D += A(16x16 bf16) * B(16x8 bf16), fp32 accum
__device__ __forceinline__ void mma16816(float* c, const uint32_t* a,
                                         uint32_t b0, uint32_t b1){
    asm volatile(
        "mma.sync.aligned.m16n8k16.row.col.f32.bf16.bf16.f32 "
        "{%0,%1,%2,%3}, {%4,%5,%6,%7}, {%8,%9}, {%0,%1,%2,%3};"
        : "+f"(c[0]), "+f"(c[1]), "+f"(c[2]), "+f"(c[3])
        : "r"(a[0]), "r"(a[1]), "r"(a[2]), "r"(a[3]), "r"(b0), "r"(b1));
}
__device__ __forceinline__ void bsplit(float2 f, uint32_t& h, uint32_t& l){
    __nv_bfloat162 hb = __float22bfloat162_rn(f);
    float2 hf = __bfloat1622float2(hb);
    __nv_bfloat162 lb = __float22bfloat162_rn(make_float2(f.x - hf.x, f.y - hf.y));
    h = *(uint32_t*)&hb; l = *(uint32_t*)&lb;
}

// ================= 1) sa_norm -> bf16 hi/lo split =================
__global__ __launch_bounds__(256) void k_norms(const float* __restrict__ sa)
{
    int warp = threadIdx.x >> 5;
    int lane = threadIdx.x & 31;
    int row = blockIdx.x * 8 + warp;
    if (row >= 64) return;
    const float4* p = (const float4*)(sa + (size_t)row * DD);
    float4 a = p[lane], b = p[lane + 32];
    float ss = a.x*a.x + a.y*a.y + a.z*a.z + a.w*a.w
             + b.x*b.x + b.y*b.y + b.z*b.z + b.w*b.w;
    ss = warpSum(ss);
    float inv = 1.0f / fmaxf(sqrtf(ss), 1e-12f);
    a.x*=inv; a.y*=inv; a.z*=inv; a.w*=inv;
    b.x*=inv; b.y*=inv; b.z*=inv; b.w*=inv;
    uint32_t* hi = (uint32_t*)g_sahi;
    uint32_t* lo = (uint32_t*)g_salo;
    float2 f[4] = {{a.x,a.y},{a.z,a.w},{b.x,b.y},{b.z,b.w}};
    int base[4] = {row*128 + lane*2, row*128 + lane*2 + 1,
                   row*128 + 64 + lane*2, row*128 + 64 + lane*2 + 1};
    #pragma unroll
    for (int i = 0; i < 4; i++) {
        uint32_t h, l;
        bsplit(f[i], h, l);
        hi[base[i]] = h;
        lo[base[i]] = l;
    }
}

// ================= 2) token projection =================
__global__ __launch_bounds__(256) void k_token(const float* __restrict__ x,
                                               const float* __restrict__ tw,
                                               const float* __restrict__ tb)
{
    int b = blockIdx.x, j = threadIdx.x;
    __shared__ float4 xs[64];
    if (j < 64) xs[j] = ((const float4*)(x + (size_t)b * NTOK * DD))[j];
    __syncthreads();
    const float4* w4 = (const float4*)(tw + (size_t)j * DD);
    float acc = tb[j];
    #pragma unroll 8
    for (int d = 0; d < 64; d++) {
        float4 wv = w4[d]; float4 xv = xs[d];
        acc += wv.x*xv.x + wv.y*xv.y + wv.z*xv.z + wv.w*xv.w;
    }
    g_t[b * DD + j] = acc;
}

// ================= 3) score via mma.sync bf16-split =================
// block: 128 tokens x 64 clusters, K=256. 8 warps, warp w = token rows 16w..16w+15.
// SMEM (words): [0, 8448) B_hi (pitch 132 w = 264 bf16/row); reused as D fp32 after MMAs
//               [8448, 16896) B_lo ; [16896, 17024) ssq/inv
#define SWB_LO 8448
#define SWB_SS 16896
#define SMEM_S ((16896 + 128) * 4)

__global__ __launch_bounds__(256) void k_s_mma(const float* __restrict__ x,
                                               const float* __restrict__ lsh)
{
    extern __shared__ uint32_t sw[];
    int tid = threadIdx.x;
    int w = tid >> 5, lane = tid & 31;
    int g = lane >> 2, t = lane & 3;
    int n0 = blockIdx.x * 128;
    int b  = blockIdx.y;

    // stage sa hi/lo (64 x 256 bf16) into padded SMEM
    #pragma unroll
    for (int it = 0; it < 8; it++) {
        int idx = tid + it * 256;
        int n = idx >> 5, c = idx & 31;
        uint4 vh = *(const uint4*)(g_sahi + n * 256 + c * 8);
        uint4 vl = *(const uint4*)(g_salo + n * 256 + c * 8);
        *(uint4*)(sw + n * 132 + c * 4)          = vh;
        *(uint4*)(sw + SWB_LO + n * 132 + c * 4) = vl;
    }
    __syncthreads();

    const float* pA0 = x + ((size_t)b * NTOK + 1 + n0 + w * 16 + g) * DD + t * 2;
    const float* pA1 = pA0 + 8 * DD;

    float acc[8][4];
    #pragma unroll
    for (int j = 0; j < 8; j++)
        #pragma unroll
        for (int i = 0; i < 4; i++) acc[j][i] = 0.f;
    float ssq0 = 0.f, ssq1 = 0.f;
    int bbase = g * 132 + t;

    #pragma unroll 2
    for (int kk = 0; kk < 16; kk++) {
        float2 f0 = *(const float2*)(pA0 + kk*16);       // row g,   k lo
        float2 f1 = *(const float2*)(pA1 + kk*16);       // row g+8, k lo
        float2 f2 = *(const float2*)(pA0 + kk*16 + 8);   // row g,   k hi
        float2 f3 = *(const float2*)(pA1 + kk*16 + 8);   // row g+8, k hi
        ssq0 += f0.x*f0.x + f0.y*f0.y + f2.x*f2.x + f2.y*f2.y;
        ssq1 += f1.x*f1.x + f1.y*f1.y + f3.x*f3.x + f3.y*f3.y;
        uint32_t ah[4], al[4];
        bsplit(f0, ah[0], al[0]);
        bsplit(f1, ah[1], al[1]);
        bsplit(f2, ah[2], al[2]);
        bsplit(f3, ah[3], al[3]);
        int kb = kk * 8 + bbase;
        #pragma unroll
        for (int j = 0; j < 8; j++) {
            uint32_t b0h = sw[j*1056 + kb];
            uint32_t b1h = sw[j*1056 + kb + 4];
            uint32_t b0l = sw[SWB_LO + j*1056 + kb];
            uint32_t b1l = sw[SWB_LO + j*1056 + kb + 4];
            mma16816(acc[j], ah, b0h, b1h);
            mma16816(acc[j], ah, b0l, b1l);
            mma16816(acc[j], al, b0h, b1h);
        }
    }

    // row ssq: sum over the 4 lanes of each group
    ssq0 += __shfl_xor_sync(0xffffffffu, ssq0, 1);
    ssq0 += __shfl_xor_sync(0xffffffffu, ssq0, 2);
    ssq1 += __shfl_xor_sync(0xffffffffu, ssq1, 1);
    ssq1 += __shfl_xor_sync(0xffffffffu, ssq1, 2);
    float* ssp = (float*)(sw + SWB_SS);
    if (t == 0) {
        ssp[w*16 + g]     = ssq0;
        ssp[w*16 + 8 + g] = ssq1;
    }
    __syncthreads();   // all B reads done -> safe to overwrite B_hi with D

    // write D transposed into SMEM: Df[n][token], pitch 132 floats
    float* Df = (float*)sw;
    int tok = w * 16 + g;
    #pragma unroll
    for (int j = 0; j < 8; j++) {
        int n = j*8 + t*2;
        Df[(size_t)n * 132 + tok]           = acc[j][0];
        Df[(size_t)(n+1) * 132 + tok]       = acc[j][1];
        Df[(size_t)n * 132 + tok + 8]       = acc[j][2];
        Df[(size_t)(n+1) * 132 + tok + 8]   = acc[j][3];
    }
    float scale = __expf(lsh[0]) * 10.0f;
    __syncthreads();
    if (tid < 128)
        ssp[tid] = scale / fmaxf(sqrtf(ssp[tid]), 1e-12f);
    __syncthreads();

    // coalesced exp + store: g_M[(b*KK+n)*NF + n0 + tok]
    #pragma unroll
    for (int it = 0; it < 8; it++) {
        int idx = tid + it * 256;
        int n = idx >> 5, c4 = (idx & 31) * 4;
        float4 v  = *(const float4*)(Df + (size_t)n * 132 + c4);
        float4 iv = *(const float4*)(ssp + c4);
        float4 r;
        r.x = __expf(v.x * iv.x);
        r.y = __expf(v.y * iv.y);
        r.z = __expf(v.z * iv.z);
        r.w = __expf(v.w * iv.w);
        *(float4*)(g_M + ((size_t)b * KK + n) * NF + n0 + c4) = r;
    }
}

// ================= 4) init =================
__global__ __launch_bounds__(256) void k_init()
{
    int i = blockIdx.x * 256 + threadIdx.x;
    if (i < BB * NF) g_ev[i] = 1.0f;
    if (i < BB * 3)  g_sevp[i] = (float)(NF / 3);
}

// ================= 5) Sinkhorn u-update =================
__global__ __launch_bounds__(192) void k_u()
{
    int bk = blockIdx.x;
    int b  = bk / KA, k = bk % KA;
    if (k == KK) {
        if (threadIdx.x == 0) {
            float sev = g_sevp[b*3+0] + g_sevp[b*3+1] + g_sevp[b*3+2];
            g_eu[b * KA + KK] = __fdividef(EXP_LOG_A, sev);
        }
        return;
    }
    const float4* E  = (const float4*)(g_M + ((size_t)b * KK + k) * NF);
    const float4* ev = (const float4*)(g_ev + (size_t)b * NF);
    int tid = threadIdx.x;
    float s = 0.f;
    #pragma unroll
    for (int it = 0; it < 3; it++) {
        int i = tid + it * 192;
        float4 e = E[i], w = ev[i];
        s += e.x*w.x + e.y*w.y + e.z*w.z + e.w*w.w;
    }
    s = warpSum(s);
    __shared__ float red[6];
    if ((tid & 31) == 0) red[tid >> 5] = s;
    __syncthreads();
    if (tid == 0) {
        float t = ((red[0]+red[1]) + (red[2]+red[3])) + (red[4]+red[5]);
        g_eu[b * KA + k] = __fdividef(EXP_LOG_A, t);
    }
}

// ================= 6) Sinkhorn v-update =================
__global__ __launch_bounds__(192) void k_v()
{
    int b  = blockIdx.y;
    int n4 = blockIdx.x * 192 + threadIdx.x;
    __shared__ float eus[KA];
    __shared__ float red[6];
    int tid = threadIdx.x;
    if (tid < KA) eus[tid] = g_eu[b * KA + tid];
    __syncthreads();
    const float4* Eb = (const float4*)(g_M + (size_t)b * KK * NF);
    float dc = eus[KK];
    float4 acc = {dc, dc, dc, dc};
    #pragma unroll 8
    for (int k = 0; k < KK; k++) {
        float4 e = Eb[(size_t)k * (NF/4) + n4];
        float u = eus[k];
        acc.x += e.x * u; acc.y += e.y * u;
        acc.z += e.z * u; acc.w += e.w * u;
    }
    float4 r;
    r.x = __fdividef(EXP_LOG_B, acc.x);
    r.y = __fdividef(EXP_LOG_B, acc.y);
    r.z = __fdividef(EXP_LOG_B, acc.z);
    r.w = __fdividef(EXP_LOG_B, acc.w);
    ((float4*)(g_ev + (size_t)b * NF))[n4] = r;

    float sp = (r.x + r.y) + (r.z + r.w);
    sp = warpSum(sp);
    if ((tid & 31) == 0) red[tid >> 5] = sp;
    __syncthreads();
    if (tid == 0)
        g_sevp[b*3 + blockIdx.x] = ((red[0]+red[1]) + (red[2]+red[3])) + (red[4]+red[5]);
}

// ================= 7) partial G = p @ fi (FFMA2) =================
__global__ __launch_bounds__(256, 2) void k_pg(const float* __restrict__ x)
{
    int q = blockIdx.x;
    int b = blockIdx.y;
    __shared__ float ps[64][33];
    __shared__ float fs[32][260];
    __shared__ float uc[64];
    __shared__ float psump[64][4];

    int tid = threadIdx.x;
    if (tid < 64) uc[tid] = g_eu[b * KA + tid];
    __syncthreads();

    int pk = tid >> 2, pq = (tid & 3) * 8;
    int trK = tid >> 5, tcC = tid & 31;
    unsigned long long acc2[8][4];
    #pragma unroll
    for (int i = 0; i < 8; i++)
        #pragma unroll
        for (int j = 0; j < 4; j++) acc2[i][j] = 0ull;
    float mypsum = 0.f;

    const float* Eb = g_M + (size_t)b * KK * NF + q * NQ;
    const float* vb = g_ev + (size_t)b * NF + q * NQ;
    const float* xb = x + ((size_t)b * NTOK + 1 + q * NQ) * DD;
    float u_k = uc[pk];

    for (int n0 = 0; n0 < NQ; n0 += 32) {
        {
            const float* Erow = Eb + (size_t)pk * NF + n0 + pq;
            const float* vrow = vb + n0 + pq;
            float4 e0 = *(const float4*)(Erow),   e1 = *(const float4*)(Erow + 4);
            float4 w0 = *(const float4*)(vrow),   w1 = *(const float4*)(vrow + 4);
            float pv[8];
            pv[0] = e0.x*u_k*w0.x; pv[1] = e0.y*u_k*w0.y;
            pv[2] = e0.z*u_k*w0.z; pv[3] = e0.w*u_k*w0.w;
            pv[4] = e1.x*u_k*w1.x; pv[5] = e1.y*u_k*w1.y;
            pv[6] = e1.z*u_k*w1.z; pv[7] = e1.w*u_k*w1.w;
            #pragma unroll
            for (int l = 0; l < 8; l++) { ps[pk][pq + l] = pv[l]; mypsum += pv[l]; }
        }
        #pragma unroll
        for (int it = 0; it < 8; it++) {
            int idx = tid + it * 256;
            int nn = idx >> 6, c4 = (idx & 63) * 4;
            float4 v = *(const float4*)(xb + (size_t)(n0 + nn) * DD + c4);
            *(float4*)&fs[nn][c4] = v;
        }
        __syncthreads();
        #pragma unroll
        for (int nn = 0; nn < 32; nn++) {
            ulonglong2 bb0 = *(const ulonglong2*)&fs[nn][tcC*8];
            ulonglong2 bb1 = *(const ulonglong2*)&fs[nn][tcC*8+4];
            #pragma unroll
            for (int i = 0; i < 8; i++) {
                unsigned long long a2;
                PACK2(a2, *(const unsigned*)&ps[trK*8 + i][nn]);
                FMA2(acc2[i][0], a2, bb0.x);
                FMA2(acc2[i][1], a2, bb0.y);
                FMA2(acc2[i][2], a2, bb1.x);
                FMA2(acc2[i][3], a2, bb1.y);
            }
        }
        __syncthreads();
    }

    psump[pk][tid & 3] = mypsum;
    __syncthreads();
    if (tid < 64)
        g_psum[((size_t)q * BB + b) * KK + tid] =
            (psump[tid][0] + psump[tid][1]) + (psump[tid][2] + psump[tid][3]);

    float* out = g_G + ((size_t)q * BB + b) * KK * DD;
    #pragma unroll
    for (int i = 0; i < 8; i++) {
        int k = trK*8 + i;
        float v0[8];
        #pragma unroll
        for (int j2 = 0; j2 < 4; j2++) {
            float2 p = u2f(acc2[i][j2]);
            v0[2*j2] = p.x; v0[2*j2+1] = p.y;
        }
        float* dst = out + (size_t)k * DD + tcC*8;
        *(float4*)dst       = *(float4*)(v0);
        *(float4*)(dst + 4) = *(float4*)(v0 + 4);
    }
}

// ================= 8) v_agg = (sum_q G) @ Wf^T + psum*(bias - agg) =================
__global__ __launch_bounds__(256) void k_vagg(const float* __restrict__ w,
                                              const float* __restrict__ bias,
                                              const float* __restrict__ aggA)
{
    int b = blockIdx.x;
    __shared__ float Gs[32][68];
    __shared__ float Ws[32][132];
    int tid = threadIdx.x;
    int trK = tid >> 4, tcC = tid & 15;
    float acc[4][8];
    #pragma unroll
    for (int i = 0; i < 4; i++)
        #pragma unroll
        for (int j = 0; j < 8; j++) acc[i][j] = 0.f;

    for (int d0 = 0; d0 < DD; d0 += 32) {
        #pragma unroll
        for (int it = 0; it < 2; it++) {
            int idx = tid + it * 256;
            int k = idx >> 3, d4 = (idx & 7) * 4;
            float4 s = {0.f, 0.f, 0.f, 0.f};
            #pragma unroll
            for (int q = 0; q < QSP; q++) {
                float4 v = *(const float4*)(g_G + ((size_t)q * BB + b) * KK * DD
                                            + (size_t)k * DD + d0 + d4);
                s.x += v.x; s.y += v.y; s.z += v.z; s.w += v.w;
            }
            Gs[d4+0][k] = s.x; Gs[d4+1][k] = s.y;
            Gs[d4+2][k] = s.z; Gs[d4+3][k] = s.w;
        }
        #pragma unroll
        for (int it = 0; it < 4; it++) {
            int idx = tid + it * 256;
            int c = idx >> 3, d4 = (idx & 7) * 4;
            float4 v = *(const float4*)(w + (size_t)c * DD + d0 + d4);
            Ws[d4+0][c] = v.x; Ws[d4+1][c] = v.y;
            Ws[d4+2][c] = v.z; Ws[d4+3][c] = v.w;
        }
        __syncthreads();
        #pragma unroll
        for (int d = 0; d < 32; d++) {
            float a[4], bb[8];
            #pragma unroll
            for (int i = 0; i < 4; i++) a[i] = Gs[d][trK*4 + i];
            *(float4*)(bb)   = *(const float4*)&Ws[d][tcC*8];
            *(float4*)(bb+4) = *(const float4*)&Ws[d][tcC*8+4];
            #pragma unroll
            for (int i = 0; i < 4; i++)
                #pragma unroll
                for (int j = 0; j < 8; j++) acc[i][j] += a[i]*bb[j];
        }
        __syncthreads();
    }

    float bi[8];
    *(float4*)(bi)   = *(const float4*)(bias + tcC*8);
    *(float4*)(bi+4) = *(const float4*)(bias + tcC*8 + 4);
    float* out = g_vagg + (size_t)b * KK * CC;
    #pragma unroll
    for (int i = 0; i < 4; i++) {
        int k = trK*4 + i;
        float psv = 0.f;
        #pragma unroll
        for (int q = 0; q < QSP; q++)
            psv += g_psum[((size_t)q * BB + b) * KK + k];
        float v0[8];
        #pragma unroll
        for (int j = 0; j < 8; j++)
            v0[j] = acc[i][j] + psv * (bi[j] - aggA[(size_t)k * CC + tcC*8 + j]);
        float* dst = out + (size_t)k * CC + tcC*8;
        *(float4*)dst       = *(float4*)(v0);
        *(float4*)(dst + 4) = *(float4*)(v0 + 4);
    }
}

// ================= 9) final concat + l2norm =================
__global__ __launch_bounds__(256) void k_out(float* __restrict__ out)
{
    int b = blockIdx.x, tid = threadIdx.x;
    const float* t  = g_t + (size_t)b * DD;
    const float* vg = g_vagg + (size_t)b * KK * CC;
    float ss = 0.f;
    #pragma unroll
    for (int it = 0; it < 33; it++) {
        int i = tid + it * 256;
        float v = (i < DD) ? t[i] : vg[i - DD];
        ss += v * v;
    }
    __shared__ float red[8];
    ss = warpSum(ss);
    if ((tid & 31) == 0) red[tid >> 5] = ss;
    __syncthreads();
    float tot = 0.f;
    #pragma unroll
    for (int i = 0; i < 8; i++) tot += red[i];
    float inv = 1.0f / fmaxf(sqrtf(tot), 1e-12f);
    float* o = out + (size_t)b * OUTD;
    #pragma unroll
    for (int it = 0; it < 33; it++) {
        int i = tid + it * 256;
        float v = (i < DD) ? t[i] : vg[i - DD];
        o[i] = v * inv;
    }
}

// ================= launch =================
extern "C" void kernel_launch(void* const* d_in, const int* in_sizes, int n_in,
                              void* d_out, int out_size)
{
    (void)in_sizes; (void)n_in; (void)out_size;
    const float* x    = (const float*)d_in[0];
    const float* fw   = (const float*)d_in[1];
    const float* fb   = (const float*)d_in[2];
    const float* tw   = (const float*)d_in[3];
    const float* tb   = (const float*)d_in[4];
    const float* sa   = (const float*)d_in[5];
    const float* agg  = (const float*)d_in[6];
    const float* lsh  = (const float*)d_in[8];
    float* out = (float*)d_out;

    cudaFuncSetAttribute(k_s_mma, cudaFuncAttributeMaxDynamicSharedMemorySize, SMEM_S);

    k_norms<<<8, 256>>>(sa);
    k_token<<<BB, 256>>>(x, tw, tb);
    k_init<<<(BB*NF)/256, 256>>>();
    k_s_mma<<<dim3(NF/128, BB), 256, SMEM_S>>>(x, lsh);
    for (int it = 0; it < NITER; it++) {
        k_u<<<BB*KA, 192>>>();
        k_v<<<dim3(3, BB), 192>>>();
    }
    k_pg<<<dim3(QSP, BB), 256>>>(x);
    k_vagg<<<BB, 256>>>(fw, fb, agg);
    k_out<<<BB, 256>>>(out);
}

// round 13
// speedup vs baseline: 2.7227x; 1.2821x over previous
#include <cuda_runtime.h>
#include <cuda_bf16.h>
#include <math_constants.h>
#include <cstdint>

// ---------------- problem constants ----------------
#define BB    64      // batch
#define NTOK  2305    // tokens incl. global token
#define NF    2304    // feature tokens (N-1)
#define DD    256     // channel dim
#define CC    128     // CLUSTER_DIM
#define KK    64      // NUM_CLUSTERS
#define KA    65      // K+1 (with dustbin)
#define NITER 5
#define OUTD  (DD + KK*CC)   // 8448
#define QSP   4              // n-splits for k_pg
#define NQ    (NF/QSP)       // 576

#define EXP_LOG_A (1.0f/65.0f)
#define EXP_LOG_B (1.0f/2304.0f)

// ---------------- scratch (device globals; no allocs allowed) ----------------
__device__ float g_M[(size_t)BB*KK*NF];        // E = exp(s/reg)
__device__ float g_eu[BB*KA];
__device__ float g_ev[BB*NF];
__device__ float g_sevp[BB*3];
__device__ float g_t[BB*DD];
__device__ float g_G[(size_t)QSP*BB*KK*DD];
__device__ float g_psum[QSP*BB*KK];
__device__ float g_vagg[(size_t)BB*KK*CC];
__device__ __align__(16) __nv_bfloat16 g_sahi[KK*DD];   // sa_norm split: hi
__device__ __align__(16) __nv_bfloat16 g_salo[KK*DD];   //               lo

// ---------------- helpers ----------------
__device__ __forceinline__ float warpSum(float v){
    #pragma unroll
    for (int o = 16; o; o >>= 1) v += __shfl_xor_sync(0xffffffffu, v, o);
    return v;
}
__device__ __forceinline__ uint32_t smem_u32(const void* p){
    uint32_t a;
    asm("{ .reg .u64 t; cvta.to.shared.u64 t, %1; cvt.u32.u64 %0, t; }" : "=r"(a) : "l"(p));
    return a;
}

// warp MMA: D += A(16x16 bf16) * B(16x8 bf16), fp32 accum
__device__ __forceinline__ void mma16816(float* c, const uint32_t* a,
                                         uint32_t b0, uint32_t b1){
    asm volatile(
        "mma.sync.aligned.m16n8k16.row.col.f32.bf16.bf16.f32 "
        "{%0,%1,%2,%3}, {%4,%5,%6,%7}, {%8,%9}, {%0,%1,%2,%3};"
        : "+f"(c[0]), "+f"(c[1]), "+f"(c[2]), "+f"(c[3])
        : "r"(a[0]), "r"(a[1]), "r"(a[2]), "r"(a[3]), "r"(b0), "r"(b1));
}
__device__ __forceinline__ void bsplit(float2 f, uint32_t& h, uint32_t& l){
    __nv_bfloat162 hb = __float22bfloat162_rn(f);
    float2 hf = __bfloat1622float2(hb);
    __nv_bfloat162 lb = __float22bfloat162_rn(make_float2(f.x - hf.x, f.y - hf.y));
    h = *(uint32_t*)&hb; l = *(uint32_t*)&lb;
}
__device__ __forceinline__ void ldsm4t(uint32_t* r, uint32_t a){
    asm volatile("ldmatrix.sync.aligned.m8n8.x4.trans.shared.b16 {%0,%1,%2,%3}, [%4];"
        : "=r"(r[0]), "=r"(r[1]), "=r"(r[2]), "=r"(r[3]) : "r"(a));
}
__device__ __forceinline__ void ldsm2t(uint32_t* r, uint32_t a){
    asm volatile("ldmatrix.sync.aligned.m8n8.x2.trans.shared.b16 {%0,%1}, [%2];"
        : "=r"(r[0]), "=r"(r[1]) : "r"(a));
}

// ================= 1) sa_norm -> bf16 hi/lo split =================
__global__ __launch_bounds__(256) void k_norms(const float* __restrict__ sa)
{
    int warp = threadIdx.x >> 5;
    int lane = threadIdx.x & 31;
    int row = blockIdx.x * 8 + warp;
    if (row >= 64) return;
    const float4* p = (const float4*)(sa + (size_t)row * DD);
    float4 a = p[lane], b = p[lane + 32];
    float ss = a.x*a.x + a.y*a.y + a.z*a.z + a.w*a.w
             + b.x*b.x + b.y*b.y + b.z*b.z + b.w*b.w;
    ss = warpSum(ss);
    float inv = 1.0f / fmaxf(sqrtf(ss), 1e-12f);
    a.x*=inv; a.y*=inv; a.z*=inv; a.w*=inv;
    b.x*=inv; b.y*=inv; b.z*=inv; b.w*=inv;
    uint32_t* hi = (uint32_t*)g_sahi;
    uint32_t* lo = (uint32_t*)g_salo;
    float2 f[4] = {{a.x,a.y},{a.z,a.w},{b.x,b.y},{b.z,b.w}};
    int base[4] = {row*128 + lane*2, row*128 + lane*2 + 1,
                   row*128 + 64 + lane*2, row*128 + 64 + lane*2 + 1};
    #pragma unroll
    for (int i = 0; i < 4; i++) {
        uint32_t h, l;
        bsplit(f[i], h, l);
        hi[base[i]] = h;
        lo[base[i]] = l;
    }
}

// ================= 2) token projection =================
__global__ __launch_bounds__(256) void k_token(const float* __restrict__ x,
                                               const float* __restrict__ tw,
                                               const float* __restrict__ tb)
{
    int b = blockIdx.x, j = threadIdx.x;
    __shared__ float4 xs[64];
    if (j < 64) xs[j] = ((const float4*)(x + (size_t)b * NTOK * DD))[j];
    __syncthreads();
    const float4* w4 = (const float4*)(tw + (size_t)j * DD);
    float acc = tb[j];
    #pragma unroll 8
    for (int d = 0; d < 64; d++) {
        float4 wv = w4[d]; float4 xv = xs[d];
        acc += wv.x*xv.x + wv.y*xv.y + wv.z*xv.z + wv.w*xv.w;
    }
    g_t[b * DD + j] = acc;
}

// ================= 3) score via mma.sync bf16-split =================
#define SWB_LO 8448
#define SWB_SS 16896
#define SMEM_S ((16896 + 128) * 4)

__global__ __launch_bounds__(256) void k_s_mma(const float* __restrict__ x,
                                               const float* __restrict__ lsh)
{
    extern __shared__ uint32_t sw[];
    int tid = threadIdx.x;
    int w = tid >> 5, lane = tid & 31;
    int g = lane >> 2, t = lane & 3;
    int n0 = blockIdx.x * 128;
    int b  = blockIdx.y;

    // stage sa hi/lo (64 x 256 bf16) into padded SMEM
    #pragma unroll
    for (int it = 0; it < 8; it++) {
        int idx = tid + it * 256;
        int n = idx >> 5, c = idx & 31;
        uint4 vh = *(const uint4*)(g_sahi + n * 256 + c * 8);
        uint4 vl = *(const uint4*)(g_salo + n * 256 + c * 8);
        *(uint4*)(sw + n * 132 + c * 4)          = vh;
        *(uint4*)(sw + SWB_LO + n * 132 + c * 4) = vl;
    }
    __syncthreads();

    const float* pA0 = x + ((size_t)b * NTOK + 1 + n0 + w * 16 + g) * DD + t * 2;
    const float* pA1 = pA0 + 8 * DD;

    float acc[8][4];
    #pragma unroll
    for (int j = 0; j < 8; j++)
        #pragma unroll
        for (int i = 0; i < 4; i++) acc[j][i] = 0.f;
    float ssq0 = 0.f, ssq1 = 0.f;
    int bbase = g * 132 + t;

    #pragma unroll 2
    for (int kk = 0; kk < 16; kk++) {
        float2 f0 = *(const float2*)(pA0 + kk*16);
        float2 f1 = *(const float2*)(pA1 + kk*16);
        float2 f2 = *(const float2*)(pA0 + kk*16 + 8);
        float2 f3 = *(const float2*)(pA1 + kk*16 + 8);
        ssq0 += f0.x*f0.x + f0.y*f0.y + f2.x*f2.x + f2.y*f2.y;
        ssq1 += f1.x*f1.x + f1.y*f1.y + f3.x*f3.x + f3.y*f3.y;
        uint32_t ah[4], al[4];
        bsplit(f0, ah[0], al[0]);
        bsplit(f1, ah[1], al[1]);
        bsplit(f2, ah[2], al[2]);
        bsplit(f3, ah[3], al[3]);
        int kb = kk * 8 + bbase;
        #pragma unroll
        for (int j = 0; j < 8; j++) {
            uint32_t b0h = sw[j*1056 + kb];
            uint32_t b1h = sw[j*1056 + kb + 4];
            uint32_t b0l = sw[SWB_LO + j*1056 + kb];
            uint32_t b1l = sw[SWB_LO + j*1056 + kb + 4];
            mma16816(acc[j], ah, b0h, b1h);
            mma16816(acc[j], ah, b0l, b1l);
            mma16816(acc[j], al, b0h, b1h);
        }
    }

    ssq0 += __shfl_xor_sync(0xffffffffu, ssq0, 1);
    ssq0 += __shfl_xor_sync(0xffffffffu, ssq0, 2);
    ssq1 += __shfl_xor_sync(0xffffffffu, ssq1, 1);
    ssq1 += __shfl_xor_sync(0xffffffffu, ssq1, 2);
    float* ssp = (float*)(sw + SWB_SS);
    if (t == 0) {
        ssp[w*16 + g]     = ssq0;
        ssp[w*16 + 8 + g] = ssq1;
    }
    __syncthreads();

    float* Df = (float*)sw;
    int tok = w * 16 + g;
    #pragma unroll
    for (int j = 0; j < 8; j++) {
        int n = j*8 + t*2;
        Df[(size_t)n * 132 + tok]           = acc[j][0];
        Df[(size_t)(n+1) * 132 + tok]       = acc[j][1];
        Df[(size_t)n * 132 + tok + 8]       = acc[j][2];
        Df[(size_t)(n+1) * 132 + tok + 8]   = acc[j][3];
    }
    float scale = __expf(lsh[0]) * 10.0f;
    __syncthreads();
    if (tid < 128)
        ssp[tid] = scale / fmaxf(sqrtf(ssp[tid]), 1e-12f);
    __syncthreads();

    #pragma unroll
    for (int it = 0; it < 8; it++) {
        int idx = tid + it * 256;
        int n = idx >> 5, c4 = (idx & 31) * 4;
        float4 v  = *(const float4*)(Df + (size_t)n * 132 + c4);
        float4 iv = *(const float4*)(ssp + c4);
        float4 r;
        r.x = __expf(v.x * iv.x);
        r.y = __expf(v.y * iv.y);
        r.z = __expf(v.z * iv.z);
        r.w = __expf(v.w * iv.w);
        *(float4*)(g_M + ((size_t)b * KK + n) * NF + n0 + c4) = r;
    }
}

// ================= 4) init =================
__global__ __launch_bounds__(256) void k_init()
{
    int i = blockIdx.x * 256 + threadIdx.x;
    if (i < BB * NF) g_ev[i] = 1.0f;
    if (i < BB * 3)  g_sevp[i] = (float)(NF / 3);
}

// ================= 5) Sinkhorn u-update =================
__global__ __launch_bounds__(192) void k_u()
{
    int bk = blockIdx.x;
    int b  = bk / KA, k = bk % KA;
    if (k == KK) {
        if (threadIdx.x == 0) {
            float sev = g_sevp[b*3+0] + g_sevp[b*3+1] + g_sevp[b*3+2];
            g_eu[b * KA + KK] = __fdividef(EXP_LOG_A, sev);
        }
        return;
    }
    const float4* E  = (const float4*)(g_M + ((size_t)b * KK + k) * NF);
    const float4* ev = (const float4*)(g_ev + (size_t)b * NF);
    int tid = threadIdx.x;
    float s = 0.f;
    #pragma unroll
    for (int it = 0; it < 3; it++) {
        int i = tid + it * 192;
        float4 e = E[i], w = ev[i];
        s += e.x*w.x + e.y*w.y + e.z*w.z + e.w*w.w;
    }
    s = warpSum(s);
    __shared__ float red[6];
    if ((tid & 31) == 0) red[tid >> 5] = s;
    __syncthreads();
    if (tid == 0) {
        float t = ((red[0]+red[1]) + (red[2]+red[3])) + (red[4]+red[5]);
        g_eu[b * KA + k] = __fdividef(EXP_LOG_A, t);
    }
}

// ================= 6) Sinkhorn v-update =================
__global__ __launch_bounds__(192) void k_v()
{
    int b  = blockIdx.y;
    int n4 = blockIdx.x * 192 + threadIdx.x;
    __shared__ float eus[KA];
    __shared__ float red[6];
    int tid = threadIdx.x;
    if (tid < KA) eus[tid] = g_eu[b * KA + tid];
    __syncthreads();
    const float4* Eb = (const float4*)(g_M + (size_t)b * KK * NF);
    float dc = eus[KK];
    float4 acc = {dc, dc, dc, dc};
    #pragma unroll 8
    for (int k = 0; k < KK; k++) {
        float4 e = Eb[(size_t)k * (NF/4) + n4];
        float u = eus[k];
        acc.x += e.x * u; acc.y += e.y * u;
        acc.z += e.z * u; acc.w += e.w * u;
    }
    float4 r;
    r.x = __fdividef(EXP_LOG_B, acc.x);
    r.y = __fdividef(EXP_LOG_B, acc.y);
    r.z = __fdividef(EXP_LOG_B, acc.z);
    r.w = __fdividef(EXP_LOG_B, acc.w);
    ((float4*)(g_ev + (size_t)b * NF))[n4] = r;

    float sp = (r.x + r.y) + (r.z + r.w);
    sp = warpSum(sp);
    if ((tid & 31) == 0) red[tid >> 5] = sp;
    __syncthreads();
    if (tid == 0)
        g_sevp[b*3 + blockIdx.x] = ((red[0]+red[1]) + (red[2]+red[3])) + (red[4]+red[5]);
}

// ================= 7) partial G = p @ fi via mma.sync =================
// G[k][d] = eu[k] * sum_n E[k][n] * (ev[n]*fi[n][d]); psum via ones-column (col 256).
// A = E (global, row-major, bf16-split in regs); B = ev*fi (SMEM, ldmatrix.x4.trans).
#define PG_PITCH 264                       // bf16 per B row: 33 tiles * 8 (bank-conflict-free ldsm)
#define PG_BUFB  (16 * PG_PITCH * 2)       // bytes per B buffer

__global__ __launch_bounds__(256, 2) void k_pg_mma(const float* __restrict__ x)
{
    __shared__ __align__(16) __nv_bfloat16 Bh[2][16][PG_PITCH];
    __shared__ __align__(16) __nv_bfloat16 Bl[2][16][PG_PITCH];
    __shared__ float evs[NQ];
    __shared__ float eus[KK];

    int q = blockIdx.x, b = blockIdx.y;
    int tid = threadIdx.x;
    int w = tid >> 5, lane = tid & 31;
    int g = lane >> 2, t = lane & 3;
    int mt = w & 3, h = w >> 2;
    int tstart = h * 17;

    // ev slice, eu, zero pad cols 257..263 of both buffers
    for (int i = tid; i < NQ; i += 256) evs[i] = g_ev[(size_t)b*NF + q*NQ + i];
    if (tid < KK) eus[tid] = g_eu[b*KA + tid];
    if (tid < 32) {
        int tk = tid & 15, bu = tid >> 4;
        #pragma unroll
        for (int c = 257; c < PG_PITCH; c++) {
            Bh[bu][tk][c] = __float2bfloat16(0.f);
            Bl[bu][tk][c] = __float2bfloat16(0.f);
        }
    }
    __syncthreads();

    const float* xb = x + ((size_t)b*NTOK + 1 + q*NQ) * DD;
    const float* Ep = g_M + ((size_t)b*KK + mt*16 + g) * NF + q*NQ + t*2;

    float acc[17][4];
    #pragma unroll
    for (int j = 0; j < 17; j++)
        #pragma unroll
        for (int i = 0; i < 4; i++) acc[j][i] = 0.f;

    // stage chunk 0 into buffer 0
    #pragma unroll
    for (int it = 0; it < 4; it++) {
        int idx = tid + it*256;
        int tk = idx >> 6, cg = idx & 63;
        float4 v = *(const float4*)(xb + (size_t)tk*DD + cg*4);
        float e = evs[tk];
        uint32_t h0,l0,h1,l1;
        bsplit(make_float2(v.x*e, v.y*e), h0, l0);
        bsplit(make_float2(v.z*e, v.w*e), h1, l1);
        *(uint2*)&Bh[0][tk][cg*4] = make_uint2(h0, h1);
        *(uint2*)&Bl[0][tk][cg*4] = make_uint2(l0, l1);
    }
    if (tid < 16) {
        float e = evs[tid];
        __nv_bfloat16 hb = __float2bfloat16(e);
        Bh[0][tid][256] = hb;
        Bl[0][tid][256] = __float2bfloat16(e - __bfloat162float(hb));
    }

    uint32_t bh_base = smem_u32(&Bh[0][0][0]);
    uint32_t bl_base = smem_u32(&Bl[0][0][0]);
    int rowA = ((lane >> 3) & 1) * 8 + (lane & 7);
    int tsel = lane >> 4;   // tile offset within an x4 pair
    uint32_t lroff = (uint32_t)rowA * (PG_PITCH*2);

    for (int ch = 0; ch < NQ/16; ch++) {
        int cur = ch & 1, nxt = cur ^ 1;
        bool more = (ch + 1 < NQ/16);
        __syncthreads();   // buffer 'cur' staged; 'nxt' free

        // prefetch x for next chunk (LDG early; consumed after MMAs)
        int tok0n = (ch+1)*16;
        float4 xn[4];
        if (more) {
            #pragma unroll
            for (int it = 0; it < 4; it++) {
                int idx = tid + it*256;
                int tk = idx >> 6, cg = idx & 63;
                xn[it] = *(const float4*)(xb + (size_t)(tok0n+tk)*DD + cg*4);
            }
        }

        // A fragments (E is L2-resident post-Sinkhorn)
        const float* pa = Ep + ch*16;
        float2 f0 = *(const float2*)(pa);
        float2 f1 = *(const float2*)(pa + 8*NF);
        float2 f2 = *(const float2*)(pa + 8);
        float2 f3 = *(const float2*)(pa + 8*NF + 8);
        uint32_t ah[4], al[4];
        bsplit(f0, ah[0], al[0]);
        bsplit(f1, ah[1], al[1]);
        bsplit(f2, ah[2], al[2]);
        bsplit(f3, ah[3], al[3]);

        uint32_t cb = (uint32_t)cur * PG_BUFB;
        #pragma unroll
        for (int jp = 0; jp < 8; jp++) {
            int tile = tstart + jp*2 + tsel;
            uint32_t ao = cb + lroff + (uint32_t)tile * 16;
            uint32_t hr[4], lr[4];
            ldsm4t(hr, bh_base + ao);
            ldsm4t(lr, bl_base + ao);
            mma16816(acc[jp*2],   ah, hr[0], hr[1]);
            mma16816(acc[jp*2],   ah, lr[0], lr[1]);
            mma16816(acc[jp*2],   al, hr[0], hr[1]);
            mma16816(acc[jp*2+1], ah, hr[2], hr[3]);
            mma16816(acc[jp*2+1], ah, lr[2], lr[3]);
            mma16816(acc[jp*2+1], al, hr[2], hr[3]);
        }
        if (h == 0) {   // tile 16 (only n-half 0)
            uint32_t ao = cb + lroff + 16u * 16;
            uint32_t hr[2], lr[2];
            ldsm2t(hr, bh_base + ao);
            ldsm2t(lr, bl_base + ao);
            mma16816(acc[16], ah, hr[0], hr[1]);
            mma16816(acc[16], ah, lr[0], lr[1]);
            mma16816(acc[16], al, hr[0], hr[1]);
        }

        // split + store next chunk into 'nxt'
        if (more) {
            #pragma unroll
            for (int it = 0; it < 4; it++) {
                int idx = tid + it*256;
                int tk = idx >> 6, cg = idx & 63;
                float e = evs[tok0n + tk];
                uint32_t h0,l0,h1,l1;
                bsplit(make_float2(xn[it].x*e, xn[it].y*e), h0, l0);
                bsplit(make_float2(xn[it].z*e, xn[it].w*e), h1, l1);
                *(uint2*)&Bh[nxt][tk][cg*4] = make_uint2(h0, h1);
                *(uint2*)&Bl[nxt][tk][cg*4] = make_uint2(l0, l1);
            }
            if (tid < 16) {
                float e = evs[tok0n + tid];
                __nv_bfloat16 hb = __float2bfloat16(e);
                Bh[nxt][tid][256] = hb;
                Bl[nxt][tid][256] = __float2bfloat16(e - __bfloat162float(hb));
            }
        }
    }

    // epilogue: apply eu, write partial G and psum
    int row0 = mt*16 + g;
    float eu0 = eus[row0], eu8 = eus[row0 + 8];
    float* Gout = g_G + ((size_t)q*BB + b) * KK * DD;
    #pragma unroll
    for (int jl = 0; jl < 17; jl++) {
        if (!(h == 1 && jl == 16)) {
            int tile = tstart + jl;
            int d0 = tile*8 + t*2;
            if (d0 < 256) {
                float2 v0 = {acc[jl][0]*eu0, acc[jl][1]*eu0};
                float2 v1 = {acc[jl][2]*eu8, acc[jl][3]*eu8};
                *(float2*)(Gout + (size_t)row0*DD + d0)     = v0;
                *(float2*)(Gout + (size_t)(row0+8)*DD + d0) = v1;
            } else if (d0 == 256) {
                g_psum[((size_t)q*BB + b)*KK + row0]     = acc[jl][0]*eu0;
                g_psum[((size_t)q*BB + b)*KK + row0 + 8] = acc[jl][2]*eu8;
            }
        }
    }
}

// ================= 8) v_agg = (sum_q G) @ Wf^T + psum*(bias - agg) =================
__global__ __launch_bounds__(256) void k_vagg(const float* __restrict__ w,
                                              const float* __restrict__ bias,
                                              const float* __restrict__ aggA)
{
    int b = blockIdx.x;
    __shared__ float Gs[32][68];
    __shared__ float Ws[32][132];
    int tid = threadIdx.x;
    int trK = tid >> 4, tcC = tid & 15;
    float acc[4][8];
    #pragma unroll
    for (int i = 0; i < 4; i++)
        #pragma unroll
        for (int j = 0; j < 8; j++) acc[i][j] = 0.f;

    for (int d0 = 0; d0 < DD; d0 += 32) {
        #pragma unroll
        for (int it = 0; it < 2; it++) {
            int idx = tid + it * 256;
            int k = idx >> 3, d4 = (idx & 7) * 4;
            float4 s = {0.f, 0.f, 0.f, 0.f};
            #pragma unroll
            for (int q = 0; q < QSP; q++) {
                float4 v = *(const float4*)(g_G + ((size_t)q * BB + b) * KK * DD
                                            + (size_t)k * DD + d0 + d4);
                s.x += v.x; s.y += v.y; s.z += v.z; s.w += v.w;
            }
            Gs[d4+0][k] = s.x; Gs[d4+1][k] = s.y;
            Gs[d4+2][k] = s.z; Gs[d4+3][k] = s.w;
        }
        #pragma unroll
        for (int it = 0; it < 4; it++) {
            int idx = tid + it * 256;
            int c = idx >> 3, d4 = (idx & 7) * 4;
            float4 v = *(const float4*)(w + (size_t)c * DD + d0 + d4);
            Ws[d4+0][c] = v.x; Ws[d4+1][c] = v.y;
            Ws[d4+2][c] = v.z; Ws[d4+3][c] = v.w;
        }
        __syncthreads();
        #pragma unroll
        for (int d = 0; d < 32; d++) {
            float a[4], bb[8];
            #pragma unroll
            for (int i = 0; i < 4; i++) a[i] = Gs[d][trK*4 + i];
            *(float4*)(bb)   = *(const float4*)&Ws[d][tcC*8];
            *(float4*)(bb+4) = *(const float4*)&Ws[d][tcC*8+4];
            #pragma unroll
            for (int i = 0; i < 4; i++)
                #pragma unroll
                for (int j = 0; j < 8; j++) acc[i][j] += a[i]*bb[j];
        }
        __syncthreads();
    }

    float bi[8];
    *(float4*)(bi)   = *(const float4*)(bias + tcC*8);
    *(float4*)(bi+4) = *(const float4*)(bias + tcC*8 + 4);
    float* out = g_vagg + (size_t)b * KK * CC;
    #pragma unroll
    for (int i = 0; i < 4; i++) {
        int k = trK*4 + i;
        float psv = 0.f;
        #pragma unroll
        for (int q = 0; q < QSP; q++)
            psv += g_psum[((size_t)q * BB + b) * KK + k];
        float v0[8];
        #pragma unroll
        for (int j = 0; j < 8; j++)
            v0[j] = acc[i][j] + psv * (bi[j] - aggA[(size_t)k * CC + tcC*8 + j]);
        float* dst = out + (size_t)k * CC + tcC*8;
        *(float4*)dst       = *(float4*)(v0);
        *(float4*)(dst + 4) = *(float4*)(v0 + 4);
    }
}

// ================= 9) final concat + l2norm =================
__global__ __launch_bounds__(256) void k_out(float* __restrict__ out)
{
    int b = blockIdx.x, tid = threadIdx.x;
    const float* t  = g_t + (size_t)b * DD;
    const float* vg = g_vagg + (size_t)b * KK * CC;
    float ss = 0.f;
    #pragma unroll
    for (int it = 0; it < 33; it++) {
        int i = tid + it * 256;
        float v = (i < DD) ? t[i] : vg[i - DD];
        ss += v * v;
    }
    __shared__ float red[8];
    ss = warpSum(ss);
    if ((tid & 31) == 0) red[tid >> 5] = ss;
    __syncthreads();
    float tot = 0.f;
    #pragma unroll
    for (int i = 0; i < 8; i++) tot += red[i];
    float inv = 1.0f / fmaxf(sqrtf(tot), 1e-12f);
    float* o = out + (size_t)b * OUTD;
    #pragma unroll
    for (int it = 0; it < 33; it++) {
        int i = tid + it * 256;
        float v = (i < DD) ? t[i] : vg[i - DD];
        o[i] = v * inv;
    }
}

// ================= launch =================
extern "C" void kernel_launch(void* const* d_in, const int* in_sizes, int n_in,
                              void* d_out, int out_size)
{
    (void)in_sizes; (void)n_in; (void)out_size;
    const float* x    = (const float*)d_in[0];
    const float* fw   = (const float*)d_in[1];
    const float* fb   = (const float*)d_in[2];
    const float* tw   = (const float*)d_in[3];
    const float* tb   = (const float*)d_in[4];
    const float* sa   = (const float*)d_in[5];
    const float* agg  = (const float*)d_in[6];
    const float* lsh  = (const float*)d_in[8];
    float* out = (float*)d_out;

    cudaFuncSetAttribute(k_s_mma, cudaFuncAttributeMaxDynamicSharedMemorySize, SMEM_S);

    k_norms<<<8, 256>>>(sa);
    k_token<<<BB, 256>>>(x, tw, tb);
    k_init<<<(BB*NF)/256, 256>>>();
    k_s_mma<<<dim3(NF/128, BB), 256, SMEM_S>>>(x, lsh);
    for (int it = 0; it < NITER; it++) {
        k_u<<<BB*KA, 192>>>();
        k_v<<<dim3(3, BB), 192>>>();
    }
    k_pg_mma<<<dim3(QSP, BB), 256>>>(x);
    k_vagg<<<BB, 256>>>(fw, fb, agg);
    k_out<<<BB, 256>>>(out);
}